// round 8
// baseline (speedup 1.0000x reference)
#include <cuda_runtime.h>
#include <cuda_bf16.h>
#include <math.h>
#include <stdint.h>

#define NB 8
#define NN 1024
#define ND 128
#define NP 16
#define KA 2048           // P*D joint contraction dim for attention
#define EPSF 1e-5f
#define NPAIRS 36         // 8*9/2 symmetric tile pairs

// ---------------------------------------------------------------------------
// Scratch (module-load allocated; no runtime allocation)
// ---------------------------------------------------------------------------
__device__ __align__(16) __nv_bfloat16 g_Ah[(size_t)NB * NN * KA];   // 32 MB
__device__ __align__(16) __nv_bfloat16 g_Al[(size_t)NB * NN * KA];   // 32 MB
__device__ __align__(16) __nv_bfloat16 g_SWh[(size_t)NB * NN * NN];  // 16 MB
__device__ __align__(16) __nv_bfloat16 g_SWl[(size_t)NB * NN * NN];  // 16 MB
__device__ __align__(16) float         g_Y[(size_t)NB * NN * NN];    // 32 MB

__device__ __forceinline__ uint32_t smem_u32(const void* p) {
    uint32_t a;
    asm("{ .reg .u64 t; cvta.to.shared.u64 t, %1; cvt.u32.u64 %0, t; }"
        : "=r"(a) : "l"(p));
    return a;
}

__device__ __forceinline__ uint32_t pack_bf2(__nv_bfloat16 a, __nv_bfloat16 b) {
    return (uint32_t)__bfloat16_as_ushort(a) | ((uint32_t)__bfloat16_as_ushort(b) << 16);
}

__device__ __forceinline__ void ldsm4(uint32_t* r, uint32_t addr) {
    asm volatile("ldmatrix.sync.aligned.m8n8.x4.shared.b16 {%0,%1,%2,%3}, [%4];"
                 : "=r"(r[0]), "=r"(r[1]), "=r"(r[2]), "=r"(r[3]) : "r"(addr));
}

__device__ __forceinline__ void mma16816(float* c, const uint32_t* a,
                                         uint32_t b0, uint32_t b1) {
    asm volatile(
        "mma.sync.aligned.m16n8k16.row.col.f32.bf16.bf16.f32 "
        "{%0,%1,%2,%3}, {%4,%5,%6,%7}, {%8,%9}, {%0,%1,%2,%3};"
        : "+f"(c[0]), "+f"(c[1]), "+f"(c[2]), "+f"(c[3])
        : "r"(a[0]), "r"(a[1]), "r"(a[2]), "r"(a[3]), "r"(b0), "r"(b1));
}

// Swizzled SMEM address for a (row, chunk) pair inside one 128x32 bf16 array:
// row stride 64B (no padding), 16B chunk c stored at c ^ ((row>>1)&3).
__device__ __forceinline__ uint32_t swz_addr(int row, int c) {
    return (uint32_t)(row * 64 + ((c ^ ((row >> 1) & 3)) << 4));
}

// ---------------------------------------------------------------------------
// Kernel 1 (merged prep):
//   blocks [0,1024):   build_A — hi/lo bf16 split of normalized ctx*w
//   blocks [1024,9216): selfwind rows, L2-normalized, hi/lo bf16 only
// ---------------------------------------------------------------------------
__global__ void __launch_bounds__(256) prep_kernel(
    const float* __restrict__ context, const float* __restrict__ weight,
    const float* __restrict__ acc_u, const float* __restrict__ acc_v,
    const float* __restrict__ uv_angle, const float* __restrict__ uv_angleACC,
    const float* __restrict__ speed,
    const float* __restrict__ dist, const float* __restrict__ angle)
{
    int tid = threadIdx.x;
    if (blockIdx.x < 1024) {
        // ---- build_A: 8 warps, 1 row each ----
        __shared__ float wsh[NP * ND];
        #pragma unroll
        for (int i = tid; i < NP * ND; i += 256) wsh[i] = weight[i];
        __syncthreads();

        int warp = tid >> 5, lane = tid & 31;
        int row = blockIdx.x * 8 + warp;
        const float4* ctx4 = reinterpret_cast<const float4*>(context + (size_t)row * ND);
        float4 c = ctx4[lane];
        const float4* w4 = reinterpret_cast<const float4*>(wsh);
        uint2* Ah2 = reinterpret_cast<uint2*>(g_Ah + (size_t)row * KA);
        uint2* Al2 = reinterpret_cast<uint2*>(g_Al + (size_t)row * KA);

        #pragma unroll
        for (int p = 0; p < NP; p++) {
            float4 wv = w4[p * 32 + lane];
            float4 pr;
            pr.x = c.x * wv.x; pr.y = c.y * wv.y; pr.z = c.z * wv.z; pr.w = c.w * wv.w;
            float s = pr.x * pr.x + pr.y * pr.y + pr.z * pr.z + pr.w * pr.w;
            #pragma unroll
            for (int o = 16; o > 0; o >>= 1) s += __shfl_xor_sync(0xffffffffu, s, o);
            float inv = 0.25f / fmaxf(sqrtf(s), 1e-12f);   // 0.25 = 1/sqrt(P)
            float v0 = pr.x * inv, v1 = pr.y * inv, v2 = pr.z * inv, v3 = pr.w * inv;
            __nv_bfloat16 h0 = __float2bfloat16(v0), h1 = __float2bfloat16(v1);
            __nv_bfloat16 h2 = __float2bfloat16(v2), h3 = __float2bfloat16(v3);
            uint2 hv; hv.x = pack_bf2(h0, h1); hv.y = pack_bf2(h2, h3);
            Ah2[p * 32 + lane] = hv;
            __nv_bfloat16 l0 = __float2bfloat16(v0 - __bfloat162float(h0));
            __nv_bfloat16 l1 = __float2bfloat16(v1 - __bfloat162float(h1));
            __nv_bfloat16 l2 = __float2bfloat16(v2 - __bfloat162float(h2));
            __nv_bfloat16 l3 = __float2bfloat16(v3 - __bfloat162float(h3));
            uint2 lv; lv.x = pack_bf2(l0, l1); lv.y = pack_bf2(l2, l3);
            Al2[p * 32 + lane] = lv;
        }
    } else {
        // ---- selfwind ----
        int row = blockIdx.x - 1024;    // b*N + n
        int n = row & (NN - 1);

        float uva = uv_angle[row];
        float au = acc_u[row], av = acc_v[row];
        float tacc = sqrtf(au * au + av * av + EPSF) * fabsf(cosf(uv_angleACC[row] - uva));
        float spd = fabsf(speed[row]);

        float vals[4];
        float ssum = 0.0f;
        #pragma unroll
        for (int j = 0; j < 4; j++) {
            int m = tid + j * 256;
            float a = angle[n * NN + m];
            float dd = dist[n * NN + m] + EPSF;
            float diag = (m == n) ? 0.5f * tacc : 0.0f;   // sigma = 0.5
            float v = spd * fabsf(cosf(a - uva) + diag) / dd;
            vals[j] = v;
            ssum += v * v;
        }
        __shared__ float red[8];
        #pragma unroll
        for (int o = 16; o > 0; o >>= 1) ssum += __shfl_xor_sync(0xffffffffu, ssum, o);
        if ((tid & 31) == 0) red[tid >> 5] = ssum;
        __syncthreads();
        float tot = 0.0f;
        #pragma unroll
        for (int w = 0; w < 8; w++) tot += red[w];
        float inv = 1.0f / fmaxf(sqrtf(tot), 1e-12f);

        __nv_bfloat16* hrow = g_SWh + (size_t)row * NN;
        __nv_bfloat16* lrow = g_SWl + (size_t)row * NN;
        #pragma unroll
        for (int j = 0; j < 4; j++) {
            int m = tid + j * 256;
            float v = vals[j] * inv;
            __nv_bfloat16 h = __float2bfloat16(v);
            hrow[m] = h;
            lrow[m] = __float2bfloat16(v - __bfloat162float(h));
        }
    }
}

// ---------------------------------------------------------------------------
// Kernel 2 (merged SYRK): mma.sync split-bf16, hi*hi + hi*lo + lo*hi, fp32 acc
//   blocks [0,288):   C = relu(A A^T), K=2048 -> d_out
//   blocks [288,576): C = 0.07*(SW SW^T) + EPS, K=1024 -> g_Y
// 128x128 tile/CTA, 8 warps (32x64), BK=32, 3-stage cp.async pipeline,
// prefetch at loop top, one __syncthreads per chunk, 2 CTAs/SM.
// ---------------------------------------------------------------------------
#define ARR_BYTES 8192             // 128 rows * 64 B (32 bf16, no pad)
#define STAGE_BYTES (4 * ARR_BYTES)     // Ah,Bh,Al,Bl = 32768
#define SYRK_SMEM (3 * STAGE_BYTES)     // 98304 (also covers 67.6KB epilogue)

__global__ void __launch_bounds__(256, 2) syrk_mma_kernel(float* __restrict__ Cout)
{
    const bool mode0 = blockIdx.x < (NB * NPAIRS);
    const int bpair = mode0 ? blockIdx.x : blockIdx.x - NB * NPAIRS;
    const int K = mode0 ? KA : NN;
    const __nv_bfloat16* __restrict__ Xh = mode0 ? g_Ah : g_SWh;
    const __nv_bfloat16* __restrict__ Xl = mode0 ? g_Al : g_SWl;
    float* __restrict__ C = mode0 ? Cout : g_Y;

    extern __shared__ char smem[];
    const uint32_t sbase = smem_u32(smem);
    const int tid = threadIdx.x;
    const int wid = tid >> 5, lane = tid & 31;
    const int wm = wid & 3, wn = wid >> 2;         // warp tile: rows wm*32, cols wn*64

    int pair = bpair % NPAIRS;
    int b = bpair / NPAIRS;
    int ti = 0;
    while (pair >= ti + 1) { pair -= (ti + 1); ti++; }
    int tj = pair;                                  // tj <= ti

    const __nv_bfloat16* pAh = Xh + ((size_t)b * NN + ti * 128) * K;
    const __nv_bfloat16* pAl = Xl + ((size_t)b * NN + ti * 128) * K;
    const __nv_bfloat16* pBh = Xh + ((size_t)b * NN + tj * 128) * K;
    const __nv_bfloat16* pBl = Xl + ((size_t)b * NN + tj * 128) * K;

    const int NC = K / 32;

    // ---- async load of one 32-wide K slab into stage `st` ----
    const int lrow = tid >> 2;           // 0..63 base row
    const int lc   = tid & 3;            // chunk 0..3
    auto load_stage = [&](int kt, int st) {
        uint32_t stb = sbase + (uint32_t)st * STAGE_BYTES;
        const __nv_bfloat16* srcs[4] = { pAh, pBh, pAl, pBl };
        #pragma unroll
        for (int arr = 0; arr < 4; arr++) {
            #pragma unroll
            for (int h = 0; h < 2; h++) {
                int row = lrow + h * 64;
                const void* src = srcs[arr] + (size_t)row * K + kt + lc * 8;
                uint32_t dst = stb + (uint32_t)arr * ARR_BYTES + swz_addr(row, lc);
                asm volatile("cp.async.cg.shared.global [%0], [%1], 16;"
                             :: "r"(dst), "l"(src));
            }
        }
        asm volatile("cp.async.commit_group;" ::: "memory");
    };

    float acc[2][8][4];
    #pragma unroll
    for (int mt = 0; mt < 2; mt++)
        #pragma unroll
        for (int j = 0; j < 8; j++)
            #pragma unroll
            for (int e = 0; e < 4; e++) acc[mt][j][e] = 0.0f;

    // Prologue: stages 0 and 1 in flight.
    load_stage(0, 0);
    load_stage(32, 1);
    asm volatile("cp.async.wait_group 1;" ::: "memory");   // stage 0 ready
    __syncthreads();

    const int arow = wm * 32 + (lane & 15);
    const int brow = wn * 64 + (lane & 15);
    const int cpart = lane >> 4;                    // which 16B chunk half

    for (int ck = 0; ck < NC; ck++) {
        // Prefetch stage ck+2 FIRST so LDGSTS issue overlaps MMA below.
        // Buffer (ck+2)%3 was last read in iter ck-1, ordered by its barrier.
        bool pf = (ck + 2 < NC);
        if (pf) load_stage((ck + 2) * 32, (ck + 2) % 3);

        int st = ck % 3;
        uint32_t stb = sbase + (uint32_t)st * STAGE_BYTES;
        #pragma unroll
        for (int ks = 0; ks < 2; ks++) {
            int c = ks * 2 + cpart;                 // chunk index 0..3
            uint32_t ah[2][4], al[2][4];
            #pragma unroll
            for (int mt = 0; mt < 2; mt++) {
                uint32_t off = swz_addr(arow + mt * 16, c);
                ldsm4(ah[mt], stb + off);                      // Ah
                ldsm4(al[mt], stb + 2 * ARR_BYTES + off);      // Al
            }
            #pragma unroll
            for (int nt = 0; nt < 4; nt++) {
                uint32_t bh[4], bl[4];
                uint32_t off = swz_addr(brow + nt * 16, c);
                ldsm4(bh, stb + ARR_BYTES + off);              // Bh
                ldsm4(bl, stb + 3 * ARR_BYTES + off);          // Bl
                #pragma unroll
                for (int mt = 0; mt < 2; mt++)
                    #pragma unroll
                    for (int jj = 0; jj < 2; jj++) {
                        float* a = acc[mt][nt * 2 + jj];
                        mma16816(a, ah[mt], bh[jj], bh[jj + 2]);
                        mma16816(a, ah[mt], bl[jj], bl[jj + 2]);
                        mma16816(a, al[mt], bh[jj], bh[jj + 2]);
                    }
            }
        }
        if (pf) asm volatile("cp.async.wait_group 1;" ::: "memory"); // ck+1 ready
        else    asm volatile("cp.async.wait_group 0;" ::: "memory");
        __syncthreads();
    }

    // ---- epilogue: transform, direct store, SMEM-transpose mirror ----
    size_t cb = (size_t)b * NN * NN;
    float* trans = reinterpret_cast<float*>(smem);     // 128 x (stride 132) f32

    #pragma unroll
    for (int mt = 0; mt < 2; mt++)
        #pragma unroll
        for (int j = 0; j < 8; j++)
            #pragma unroll
            for (int rh = 0; rh < 2; rh++) {
                float x0 = acc[mt][j][rh * 2], x1 = acc[mt][j][rh * 2 + 1];
                float v0, v1;
                if (mode0) { v0 = (x0 > 0.0f) ? x0 : 0.0f;
                             v1 = (x1 > 0.0f) ? x1 : 0.0f; }
                else       { v0 = 0.07f * x0 + EPSF;
                             v1 = 0.07f * x1 + EPSF; }
                int gmL = wm * 32 + mt * 16 + (lane >> 2) + rh * 8;
                int gnL = wn * 64 + j * 8 + (lane & 3) * 2;
                float2 v2 = make_float2(v0, v1);
                *reinterpret_cast<float2*>(
                    C + cb + (size_t)(ti * 128 + gmL) * NN + tj * 128 + gnL) = v2;
                if (ti != tj) {
                    trans[gnL * 132 + gmL] = v0;
                    trans[(gnL + 1) * 132 + gmL] = v1;
                }
            }
    __syncthreads();

    if (ti != tj) {
        #pragma unroll
        for (int i = 0; i < 16; i++) {
            int flat = tid + i * 256;               // 4096 float4s
            int r = flat >> 5, c4 = flat & 31;
            const float* tr = trans + r * 132 + c4 * 4;
            float4 v = make_float4(tr[0], tr[1], tr[2], tr[3]);
            *reinterpret_cast<float4*>(
                C + cb + (size_t)(tj * 128 + r) * NN + ti * 128 + c4 * 4) = v;
        }
    }
}

// ---------------------------------------------------------------------------
// Kernel 3: per-row: y=l2norm(Y); u=l2norm(|0.5*SW+sqrt(y)|+EPS); out *= u
// SW reconstructed from hi/lo bf16.
// ---------------------------------------------------------------------------
__global__ void __launch_bounds__(256) final_kernel(float* __restrict__ out)
{
    int row = blockIdx.x;
    int tid = threadIdx.x;
    const float* yrow = g_Y + (size_t)row * NN;
    const __nv_bfloat16* hrow = g_SWh + (size_t)row * NN;
    const __nv_bfloat16* lrow = g_SWl + (size_t)row * NN;
    float* orow = out + (size_t)row * NN;

    __shared__ float red[8];

    float yv[4];
    float s1 = 0.0f;
    #pragma unroll
    for (int j = 0; j < 4; j++) {
        float y = yrow[tid + j * 256];
        yv[j] = y;
        s1 += y * y;
    }
    #pragma unroll
    for (int o = 16; o > 0; o >>= 1) s1 += __shfl_xor_sync(0xffffffffu, s1, o);
    if ((tid & 31) == 0) red[tid >> 5] = s1;
    __syncthreads();
    float yt = 0.0f;
    #pragma unroll
    for (int w = 0; w < 8; w++) yt += red[w];
    float yin = 1.0f / fmaxf(sqrtf(yt), 1e-12f);
    __syncthreads();

    float tv[4];
    float s2 = 0.0f;
    #pragma unroll
    for (int j = 0; j < 4; j++) {
        int m = tid + j * 256;
        float sw = __bfloat162float(hrow[m]) + __bfloat162float(lrow[m]);
        float t = fabsf(0.5f * sw + sqrtf(yv[j] * yin)) + EPSF;
        tv[j] = t;
        s2 += t * t;
    }
    #pragma unroll
    for (int o = 16; o > 0; o >>= 1) s2 += __shfl_xor_sync(0xffffffffu, s2, o);
    if ((tid & 31) == 0) red[tid >> 5] = s2;
    __syncthreads();
    float tt = 0.0f;
    #pragma unroll
    for (int w = 0; w < 8; w++) tt += red[w];
    float tin = 1.0f / fmaxf(sqrtf(tt), 1e-12f);

    #pragma unroll
    for (int j = 0; j < 4; j++) {
        int m = tid + j * 256;
        orow[m] = orow[m] * (tv[j] * tin);
    }
}

// ---------------------------------------------------------------------------
extern "C" void kernel_launch(void* const* d_in, const int* in_sizes, int n_in,
                              void* d_out, int out_size)
{
    const float* context     = (const float*)d_in[0];  // (8,1024,128)
    const float* acc_u       = (const float*)d_in[1];
    const float* acc_v       = (const float*)d_in[2];
    const float* uv_angle    = (const float*)d_in[3];
    const float* uv_angleACC = (const float*)d_in[4];
    const float* speed       = (const float*)d_in[5];
    // d_in[6] = isPhy (unused)
    const float* dist        = (const float*)d_in[7];  // (1024,1024)
    const float* angle       = (const float*)d_in[8];  // (1024,1024)
    const float* weight      = (const float*)d_in[9];  // (16,128)
    float* out = (float*)d_out;                        // (8,1024,1024)

    cudaFuncSetAttribute((const void*)&syrk_mma_kernel,
                         cudaFuncAttributeMaxDynamicSharedMemorySize, SYRK_SMEM);

    prep_kernel<<<1024 + NB * NN, 256>>>(context, weight, acc_u, acc_v,
                                         uv_angle, uv_angleACC, speed, dist, angle);
    syrk_mma_kernel<<<2 * NB * NPAIRS, 256, SYRK_SMEM>>>(out);
    final_kernel<<<NB * NN, 256>>>(out);
}

// round 9
// speedup vs baseline: 2.0936x; 2.0936x over previous
#include <cuda_runtime.h>
#include <cuda_bf16.h>
#include <cuda_fp16.h>
#include <math.h>
#include <stdint.h>

#define NB 8
#define NN 1024
#define ND 128
#define NP 16
#define KA 2048           // P*D joint contraction dim for attention
#define EPSF 1e-5f
#define NPAIRS 36         // 8*9/2 symmetric tile pairs

// ---------------------------------------------------------------------------
// Scratch (module-load allocated; no runtime allocation)
// ---------------------------------------------------------------------------
__device__ __align__(16) __half g_A [(size_t)NB * NN * KA];   // 33.5 MB fp16
__device__ __align__(16) __half g_SWf[(size_t)NB * NN * NN];  // 16.8 MB fp16
__device__ __align__(16) float  g_Y [(size_t)NB * NN * NN];   // 33.5 MB fp32

__device__ __forceinline__ uint32_t smem_u32(const void* p) {
    uint32_t a;
    asm("{ .reg .u64 t; cvta.to.shared.u64 t, %1; cvt.u32.u64 %0, t; }"
        : "=r"(a) : "l"(p));
    return a;
}

__device__ __forceinline__ uint32_t pack_h2(float a, float b) {
    __half2 h = __floats2half2_rn(a, b);
    return *reinterpret_cast<uint32_t*>(&h);
}

__device__ __forceinline__ void ldsm4(uint32_t* r, uint32_t addr) {
    asm volatile("ldmatrix.sync.aligned.m8n8.x4.shared.b16 {%0,%1,%2,%3}, [%4];"
                 : "=r"(r[0]), "=r"(r[1]), "=r"(r[2]), "=r"(r[3]) : "r"(addr));
}

__device__ __forceinline__ void mma16816(float* c, const uint32_t* a,
                                         uint32_t b0, uint32_t b1) {
    asm volatile(
        "mma.sync.aligned.m16n8k16.row.col.f32.f16.f16.f32 "
        "{%0,%1,%2,%3}, {%4,%5,%6,%7}, {%8,%9}, {%0,%1,%2,%3};"
        : "+f"(c[0]), "+f"(c[1]), "+f"(c[2]), "+f"(c[3])
        : "r"(a[0]), "r"(a[1]), "r"(a[2]), "r"(a[3]), "r"(b0), "r"(b1));
}

// Swizzled SMEM offset inside one 128-row x 128-byte fp16 array:
// 16B chunk c (0..7) of row stored at slot c ^ (row & 7).
__device__ __forceinline__ uint32_t swz8(int row, int c) {
    return (uint32_t)(row * 128 + ((c ^ (row & 7)) << 4));
}

// ---------------------------------------------------------------------------
// Kernel 1 (merged prep):
//   blocks [0,1024):    build_A — fp16 normalized ctx*w features
//   blocks [1024,9216): selfwind rows, L2-normalized, fp16
// ---------------------------------------------------------------------------
__global__ void __launch_bounds__(256) prep_kernel(
    const float* __restrict__ context, const float* __restrict__ weight,
    const float* __restrict__ acc_u, const float* __restrict__ acc_v,
    const float* __restrict__ uv_angle, const float* __restrict__ uv_angleACC,
    const float* __restrict__ speed,
    const float* __restrict__ dist, const float* __restrict__ angle)
{
    int tid = threadIdx.x;
    if (blockIdx.x < 1024) {
        __shared__ float wsh[NP * ND];
        #pragma unroll
        for (int i = tid; i < NP * ND; i += 256) wsh[i] = weight[i];
        __syncthreads();

        int warp = tid >> 5, lane = tid & 31;
        int row = blockIdx.x * 8 + warp;
        const float4* ctx4 = reinterpret_cast<const float4*>(context + (size_t)row * ND);
        float4 c = ctx4[lane];
        const float4* w4 = reinterpret_cast<const float4*>(wsh);
        uint2* A2 = reinterpret_cast<uint2*>(g_A + (size_t)row * KA);

        #pragma unroll
        for (int p = 0; p < NP; p++) {
            float4 wv = w4[p * 32 + lane];
            float4 pr;
            pr.x = c.x * wv.x; pr.y = c.y * wv.y; pr.z = c.z * wv.z; pr.w = c.w * wv.w;
            float s = pr.x * pr.x + pr.y * pr.y + pr.z * pr.z + pr.w * pr.w;
            #pragma unroll
            for (int o = 16; o > 0; o >>= 1) s += __shfl_xor_sync(0xffffffffu, s, o);
            float inv = 0.25f / fmaxf(sqrtf(s), 1e-12f);   // 0.25 = 1/sqrt(P)
            uint2 hv;
            hv.x = pack_h2(pr.x * inv, pr.y * inv);
            hv.y = pack_h2(pr.z * inv, pr.w * inv);
            A2[p * 32 + lane] = hv;
        }
    } else {
        int row = blockIdx.x - 1024;    // b*N + n
        int n = row & (NN - 1);

        float uva = uv_angle[row];
        float au = acc_u[row], av = acc_v[row];
        float tacc = sqrtf(au * au + av * av + EPSF) * fabsf(cosf(uv_angleACC[row] - uva));
        float spd = fabsf(speed[row]);

        float vals[4];
        float ssum = 0.0f;
        #pragma unroll
        for (int j = 0; j < 4; j++) {
            int m = tid + j * 256;
            float a = angle[n * NN + m];
            float dd = dist[n * NN + m] + EPSF;
            float diag = (m == n) ? 0.5f * tacc : 0.0f;   // sigma = 0.5
            float v = spd * fabsf(cosf(a - uva) + diag) / dd;
            vals[j] = v;
            ssum += v * v;
        }
        __shared__ float red[8];
        #pragma unroll
        for (int o = 16; o > 0; o >>= 1) ssum += __shfl_xor_sync(0xffffffffu, ssum, o);
        if ((tid & 31) == 0) red[tid >> 5] = ssum;
        __syncthreads();
        float tot = 0.0f;
        #pragma unroll
        for (int w = 0; w < 8; w++) tot += red[w];
        float inv = 1.0f / fmaxf(sqrtf(tot), 1e-12f);

        __half* hrow = g_SWf + (size_t)row * NN;
        #pragma unroll
        for (int j = 0; j < 4; j++) {
            int m = tid + j * 256;
            hrow[m] = __float2half_rn(vals[j] * inv);
        }
    }
}

// ---------------------------------------------------------------------------
// Kernel 2 (merged SYRK, single-pass fp16, fp32 accumulate):
//   blocks [0,288):   C = relu(A A^T), K=2048 -> d_out
//   blocks [288,576): C = 0.07*(SW SW^T) + EPS, K=1024 -> g_Y
// 128x128 tile/CTA, 8 warps (32x64), BK=64, 3-stage cp.async pipeline,
// one __syncthreads per chunk, 2 CTAs/SM.
// ---------------------------------------------------------------------------
#define ARR_BYTES 16384                 // 128 rows * 128 B (64 fp16)
#define STAGE_BYTES (2 * ARR_BYTES)     // A, B = 32768
#define SYRK_SMEM (3 * STAGE_BYTES)     // 98304 (covers 67.6KB epilogue too)

__global__ void __launch_bounds__(256, 2) syrk_mma_kernel(float* __restrict__ Cout)
{
    const bool mode0 = blockIdx.x < (NB * NPAIRS);
    const int bpair = mode0 ? blockIdx.x : blockIdx.x - NB * NPAIRS;
    const int K = mode0 ? KA : NN;
    const __half* __restrict__ X = mode0 ? g_A : g_SWf;
    float* __restrict__ C = mode0 ? Cout : g_Y;

    extern __shared__ char smem[];
    const uint32_t sbase = smem_u32(smem);
    const int tid = threadIdx.x;
    const int wid = tid >> 5, lane = tid & 31;
    const int wm = wid & 3, wn = wid >> 2;         // warp tile: rows wm*32, cols wn*64

    int pair = bpair % NPAIRS;
    int b = bpair / NPAIRS;
    int ti = 0;
    while (pair >= ti + 1) { pair -= (ti + 1); ti++; }
    int tj = pair;                                  // tj <= ti

    const __half* pA = X + ((size_t)b * NN + ti * 128) * K;
    const __half* pB = X + ((size_t)b * NN + tj * 128) * K;

    const int NC = K / 64;

    // ---- async load of one 64-wide K slab (A + B) into stage `st` ----
    auto load_stage = [&](int kt, int st) {
        uint32_t stb = sbase + (uint32_t)st * STAGE_BYTES;
        const __half* srcs[2] = { pA, pB };
        #pragma unroll
        for (int arr = 0; arr < 2; arr++) {
            #pragma unroll
            for (int i = 0; i < 4; i++) {
                int g = i * 256 + tid;              // 0..1023 chunk id
                int row = g >> 3, c = g & 7;
                const void* src = srcs[arr] + (size_t)row * K + kt + c * 8;
                uint32_t dst = stb + (uint32_t)arr * ARR_BYTES + swz8(row, c);
                asm volatile("cp.async.cg.shared.global [%0], [%1], 16;"
                             :: "r"(dst), "l"(src));
            }
        }
        asm volatile("cp.async.commit_group;" ::: "memory");
    };

    float acc[2][8][4];
    #pragma unroll
    for (int mt = 0; mt < 2; mt++)
        #pragma unroll
        for (int j = 0; j < 8; j++)
            #pragma unroll
            for (int e = 0; e < 4; e++) acc[mt][j][e] = 0.0f;

    load_stage(0, 0);
    load_stage(64, 1);
    asm volatile("cp.async.wait_group 1;" ::: "memory");   // stage 0 ready
    __syncthreads();

    const int arow = wm * 32 + (lane & 15);
    const int brow = wn * 64 + (lane & 15);
    const int cpart = lane >> 4;                    // 16B half within K16

    for (int ck = 0; ck < NC; ck++) {
        // Prefetch stage ck+2 (buffer (ck+2)%3 last read in iter ck-1,
        // ordered by that iteration's barrier) — overlaps MMAs below.
        bool pf = (ck + 2 < NC);
        if (pf) load_stage((ck + 2) * 64, (ck + 2) % 3);

        int st = ck % 3;
        uint32_t stb = sbase + (uint32_t)st * STAGE_BYTES;
        #pragma unroll
        for (int ks = 0; ks < 4; ks++) {
            int cb = ks * 2 + cpart;                // chunk index 0..7
            uint32_t a[2][4];
            #pragma unroll
            for (int mt = 0; mt < 2; mt++) {
                int r = arow + mt * 16;
                ldsm4(a[mt], stb + swz8(r, cb));
            }
            #pragma unroll
            for (int nt = 0; nt < 4; nt++) {
                uint32_t bf[4];
                int r = brow + nt * 16;
                ldsm4(bf, stb + ARR_BYTES + swz8(r, cb));
                #pragma unroll
                for (int mt = 0; mt < 2; mt++)
                    #pragma unroll
                    for (int jj = 0; jj < 2; jj++)
                        mma16816(acc[mt][nt * 2 + jj], a[mt], bf[jj], bf[jj + 2]);
            }
        }
        if (pf) asm volatile("cp.async.wait_group 1;" ::: "memory"); // ck+1 ready
        else    asm volatile("cp.async.wait_group 0;" ::: "memory");
        __syncthreads();
    }

    // ---- epilogue: transform, direct store, SMEM-transpose mirror ----
    size_t cbo = (size_t)b * NN * NN;
    float* trans = reinterpret_cast<float*>(smem);     // 128 x (stride 132) f32

    #pragma unroll
    for (int mt = 0; mt < 2; mt++)
        #pragma unroll
        for (int j = 0; j < 8; j++)
            #pragma unroll
            for (int rh = 0; rh < 2; rh++) {
                float x0 = acc[mt][j][rh * 2], x1 = acc[mt][j][rh * 2 + 1];
                float v0, v1;
                if (mode0) { v0 = (x0 > 0.0f) ? x0 : 0.0f;
                             v1 = (x1 > 0.0f) ? x1 : 0.0f; }
                else       { v0 = 0.07f * x0 + EPSF;
                             v1 = 0.07f * x1 + EPSF; }
                int gmL = wm * 32 + mt * 16 + (lane >> 2) + rh * 8;
                int gnL = wn * 64 + j * 8 + (lane & 3) * 2;
                float2 v2 = make_float2(v0, v1);
                *reinterpret_cast<float2*>(
                    C + cbo + (size_t)(ti * 128 + gmL) * NN + tj * 128 + gnL) = v2;
                if (ti != tj) {
                    trans[gnL * 132 + gmL] = v0;
                    trans[(gnL + 1) * 132 + gmL] = v1;
                }
            }
    __syncthreads();

    if (ti != tj) {
        #pragma unroll
        for (int i = 0; i < 16; i++) {
            int flat = tid + i * 256;               // 4096 float4s
            int r = flat >> 5, c4 = flat & 31;
            const float* tr = trans + r * 132 + c4 * 4;
            float4 v = make_float4(tr[0], tr[1], tr[2], tr[3]);
            *reinterpret_cast<float4*>(
                C + cbo + (size_t)(tj * 128 + r) * NN + ti * 128 + c4 * 4) = v;
        }
    }
}

// ---------------------------------------------------------------------------
// Kernel 3: per-row: y=l2norm(Y); u=l2norm(|0.5*SW+sqrt(y)|+EPS); out *= u
// ---------------------------------------------------------------------------
__global__ void __launch_bounds__(256) final_kernel(float* __restrict__ out)
{
    int row = blockIdx.x;
    int tid = threadIdx.x;
    const float* yrow = g_Y + (size_t)row * NN;
    const __half* hrow = g_SWf + (size_t)row * NN;
    float* orow = out + (size_t)row * NN;

    __shared__ float red[8];

    float yv[4];
    float s1 = 0.0f;
    #pragma unroll
    for (int j = 0; j < 4; j++) {
        float y = yrow[tid + j * 256];
        yv[j] = y;
        s1 += y * y;
    }
    #pragma unroll
    for (int o = 16; o > 0; o >>= 1) s1 += __shfl_xor_sync(0xffffffffu, s1, o);
    if ((tid & 31) == 0) red[tid >> 5] = s1;
    __syncthreads();
    float yt = 0.0f;
    #pragma unroll
    for (int w = 0; w < 8; w++) yt += red[w];
    float yin = 1.0f / fmaxf(sqrtf(yt), 1e-12f);
    __syncthreads();

    float tv[4];
    float s2 = 0.0f;
    #pragma unroll
    for (int j = 0; j < 4; j++) {
        int m = tid + j * 256;
        float sw = __half2float(hrow[m]);
        float t = fabsf(0.5f * sw + sqrtf(yv[j] * yin)) + EPSF;
        tv[j] = t;
        s2 += t * t;
    }
    #pragma unroll
    for (int o = 16; o > 0; o >>= 1) s2 += __shfl_xor_sync(0xffffffffu, s2, o);
    if ((tid & 31) == 0) red[tid >> 5] = s2;
    __syncthreads();
    float tt = 0.0f;
    #pragma unroll
    for (int w = 0; w < 8; w++) tt += red[w];
    float tin = 1.0f / fmaxf(sqrtf(tt), 1e-12f);

    #pragma unroll
    for (int j = 0; j < 4; j++) {
        int m = tid + j * 256;
        orow[m] = orow[m] * (tv[j] * tin);
    }
}

// ---------------------------------------------------------------------------
extern "C" void kernel_launch(void* const* d_in, const int* in_sizes, int n_in,
                              void* d_out, int out_size)
{
    const float* context     = (const float*)d_in[0];  // (8,1024,128)
    const float* acc_u       = (const float*)d_in[1];
    const float* acc_v       = (const float*)d_in[2];
    const float* uv_angle    = (const float*)d_in[3];
    const float* uv_angleACC = (const float*)d_in[4];
    const float* speed       = (const float*)d_in[5];
    // d_in[6] = isPhy (unused)
    const float* dist        = (const float*)d_in[7];  // (1024,1024)
    const float* angle       = (const float*)d_in[8];  // (1024,1024)
    const float* weight      = (const float*)d_in[9];  // (16,128)
    float* out = (float*)d_out;                        // (8,1024,1024)

    cudaFuncSetAttribute((const void*)&syrk_mma_kernel,
                         cudaFuncAttributeMaxDynamicSharedMemorySize, SYRK_SMEM);

    prep_kernel<<<1024 + NB * NN, 256>>>(context, weight, acc_u, acc_v,
                                         uv_angle, uv_angleACC, speed, dist, angle);
    syrk_mma_kernel<<<2 * NB * NPAIRS, 256, SYRK_SMEM>>>(out);
    final_kernel<<<NB * NN, 256>>>(out);
}

// round 10
// speedup vs baseline: 2.1770x; 1.0399x over previous
#include <cuda_runtime.h>
#include <cuda_bf16.h>
#include <cuda_fp16.h>
#include <math.h>
#include <stdint.h>

#define NB 8
#define NN 1024
#define ND 128
#define NP 16
#define KA 2048           // P*D joint contraction dim for attention
#define EPSF 1e-5f
#define NPAIRS 36         // 8*9/2 symmetric tile pairs

// ---------------------------------------------------------------------------
// Scratch (module-load allocated; no runtime allocation)
// ---------------------------------------------------------------------------
__device__ __align__(16) __half g_A [(size_t)NB * NN * KA];   // 33.5 MB fp16
__device__ __align__(16) __half g_SWf[(size_t)NB * NN * NN];  // 16.8 MB fp16
__device__ __align__(16) float  g_Y [(size_t)NB * NN * NN];   // 33.5 MB fp32

__device__ __forceinline__ uint32_t smem_u32(const void* p) {
    uint32_t a;
    asm("{ .reg .u64 t; cvta.to.shared.u64 t, %1; cvt.u32.u64 %0, t; }"
        : "=r"(a) : "l"(p));
    return a;
}

__device__ __forceinline__ uint32_t pack_h2(float a, float b) {
    __half2 h = __floats2half2_rn(a, b);
    return *reinterpret_cast<uint32_t*>(&h);
}

__device__ __forceinline__ void ldsm4(uint32_t* r, uint32_t addr) {
    asm volatile("ldmatrix.sync.aligned.m8n8.x4.shared.b16 {%0,%1,%2,%3}, [%4];"
                 : "=r"(r[0]), "=r"(r[1]), "=r"(r[2]), "=r"(r[3]) : "r"(addr));
}

__device__ __forceinline__ void mma16816(float* c, const uint32_t* a,
                                         uint32_t b0, uint32_t b1) {
    asm volatile(
        "mma.sync.aligned.m16n8k16.row.col.f32.f16.f16.f32 "
        "{%0,%1,%2,%3}, {%4,%5,%6,%7}, {%8,%9}, {%0,%1,%2,%3};"
        : "+f"(c[0]), "+f"(c[1]), "+f"(c[2]), "+f"(c[3])
        : "r"(a[0]), "r"(a[1]), "r"(a[2]), "r"(a[3]), "r"(b0), "r"(b1));
}

// Swizzled SMEM offset inside one 128-row x 128-byte fp16 array:
// 16B chunk c (0..7) of row stored at slot c ^ (row & 7).
__device__ __forceinline__ uint32_t swz8(int row, int c) {
    return (uint32_t)(row * 128 + ((c ^ (row & 7)) << 4));
}

// ---------------------------------------------------------------------------
// Kernel 1 (merged prep):
//   blocks [0,1024):    build_A — fp16 normalized ctx*w features
//   blocks [1024,9216): selfwind rows, L2-normalized, fp16 (MUFU cos)
// ---------------------------------------------------------------------------
__global__ void __launch_bounds__(256) prep_kernel(
    const float* __restrict__ context, const float* __restrict__ weight,
    const float* __restrict__ acc_u, const float* __restrict__ acc_v,
    const float* __restrict__ uv_angle, const float* __restrict__ uv_angleACC,
    const float* __restrict__ speed,
    const float* __restrict__ dist, const float* __restrict__ angle)
{
    int tid = threadIdx.x;
    if (blockIdx.x < 1024) {
        __shared__ float wsh[NP * ND];
        #pragma unroll
        for (int i = tid; i < NP * ND; i += 256) wsh[i] = weight[i];
        __syncthreads();

        int warp = tid >> 5, lane = tid & 31;
        int row = blockIdx.x * 8 + warp;
        const float4* ctx4 = reinterpret_cast<const float4*>(context + (size_t)row * ND);
        float4 c = ctx4[lane];
        const float4* w4 = reinterpret_cast<const float4*>(wsh);
        uint2* A2 = reinterpret_cast<uint2*>(g_A + (size_t)row * KA);

        #pragma unroll
        for (int p = 0; p < NP; p++) {
            float4 wv = w4[p * 32 + lane];
            float4 pr;
            pr.x = c.x * wv.x; pr.y = c.y * wv.y; pr.z = c.z * wv.z; pr.w = c.w * wv.w;
            float s = pr.x * pr.x + pr.y * pr.y + pr.z * pr.z + pr.w * pr.w;
            #pragma unroll
            for (int o = 16; o > 0; o >>= 1) s += __shfl_xor_sync(0xffffffffu, s, o);
            float inv = 0.25f / fmaxf(sqrtf(s), 1e-12f);   // 0.25 = 1/sqrt(P)
            uint2 hv;
            hv.x = pack_h2(pr.x * inv, pr.y * inv);
            hv.y = pack_h2(pr.z * inv, pr.w * inv);
            A2[p * 32 + lane] = hv;
        }
    } else {
        int row = blockIdx.x - 1024;    // b*N + n
        int n = row & (NN - 1);

        float uva = uv_angle[row];
        float au = acc_u[row], av = acc_v[row];
        float tacc = sqrtf(au * au + av * av + EPSF) * fabsf(__cosf(uv_angleACC[row] - uva));
        float spd = fabsf(speed[row]);

        float vals[4];
        float ssum = 0.0f;
        #pragma unroll
        for (int j = 0; j < 4; j++) {
            int m = tid + j * 256;
            float a = angle[n * NN + m];
            float dd = dist[n * NN + m] + EPSF;
            float diag = (m == n) ? 0.5f * tacc : 0.0f;   // sigma = 0.5
            float v = spd * __fdividef(fabsf(__cosf(a - uva) + diag), dd);
            vals[j] = v;
            ssum += v * v;
        }
        __shared__ float red[8];
        #pragma unroll
        for (int o = 16; o > 0; o >>= 1) ssum += __shfl_xor_sync(0xffffffffu, ssum, o);
        if ((tid & 31) == 0) red[tid >> 5] = ssum;
        __syncthreads();
        float tot = 0.0f;
        #pragma unroll
        for (int w = 0; w < 8; w++) tot += red[w];
        float inv = 1.0f / fmaxf(sqrtf(tot), 1e-12f);

        __half* hrow = g_SWf + (size_t)row * NN;
        #pragma unroll
        for (int j = 0; j < 4; j++) {
            int m = tid + j * 256;
            hrow[m] = __float2half_rn(vals[j] * inv);
        }
    }
}

// ---------------------------------------------------------------------------
// Kernel 2 (merged SYRK, single-pass fp16, fp32 accumulate):
//   blocks [0,288):   C = relu(A A^T), K=2048 -> d_out
//   blocks [288,576): C = 0.07*(SW SW^T) + EPS, K=1024 -> g_Y
// 128x128 tile/CTA, 8 warps (32x64), BK=64, 3-stage cp.async pipeline,
// one __syncthreads per chunk, 2 CTAs/SM.
// ---------------------------------------------------------------------------
#define ARR_BYTES 16384                 // 128 rows * 128 B (64 fp16)
#define STAGE_BYTES (2 * ARR_BYTES)     // A, B = 32768
#define SYRK_SMEM (3 * STAGE_BYTES)     // 98304 (covers 67.6KB epilogue too)

__global__ void __launch_bounds__(256, 2) syrk_mma_kernel(float* __restrict__ Cout)
{
    const bool mode0 = blockIdx.x < (NB * NPAIRS);
    const int bpair = mode0 ? blockIdx.x : blockIdx.x - NB * NPAIRS;
    const int K = mode0 ? KA : NN;
    const __half* __restrict__ X = mode0 ? g_A : g_SWf;
    float* __restrict__ C = mode0 ? Cout : g_Y;

    extern __shared__ char smem[];
    const uint32_t sbase = smem_u32(smem);
    const int tid = threadIdx.x;
    const int wid = tid >> 5, lane = tid & 31;
    const int wm = wid & 3, wn = wid >> 2;         // warp tile: rows wm*32, cols wn*64

    int pair = bpair % NPAIRS;
    int b = bpair / NPAIRS;
    int ti = 0;
    while (pair >= ti + 1) { pair -= (ti + 1); ti++; }
    int tj = pair;                                  // tj <= ti

    const __half* pA = X + ((size_t)b * NN + ti * 128) * K;
    const __half* pB = X + ((size_t)b * NN + tj * 128) * K;

    const int NC = K / 64;

    // ---- async load of one 64-wide K slab (A + B) into stage `st` ----
    auto load_stage = [&](int kt, int st) {
        uint32_t stb = sbase + (uint32_t)st * STAGE_BYTES;
        const __half* srcs[2] = { pA, pB };
        #pragma unroll
        for (int arr = 0; arr < 2; arr++) {
            #pragma unroll
            for (int i = 0; i < 4; i++) {
                int g = i * 256 + tid;              // 0..1023 chunk id
                int row = g >> 3, c = g & 7;
                const void* src = srcs[arr] + (size_t)row * K + kt + c * 8;
                uint32_t dst = stb + (uint32_t)arr * ARR_BYTES + swz8(row, c);
                asm volatile("cp.async.cg.shared.global [%0], [%1], 16;"
                             :: "r"(dst), "l"(src));
            }
        }
        asm volatile("cp.async.commit_group;" ::: "memory");
    };

    float acc[2][8][4];
    #pragma unroll
    for (int mt = 0; mt < 2; mt++)
        #pragma unroll
        for (int j = 0; j < 8; j++)
            #pragma unroll
            for (int e = 0; e < 4; e++) acc[mt][j][e] = 0.0f;

    load_stage(0, 0);
    load_stage(64, 1);
    asm volatile("cp.async.wait_group 1;" ::: "memory");   // stage 0 ready
    __syncthreads();

    const int arow = wm * 32 + (lane & 15);
    const int brow = wn * 64 + (lane & 15);
    const int cpart = lane >> 4;                    // 16B half within K16

    for (int ck = 0; ck < NC; ck++) {
        // Prefetch stage ck+2 (buffer (ck+2)%3 last read in iter ck-1,
        // ordered by that iteration's barrier) — overlaps MMAs below.
        bool pf = (ck + 2 < NC);
        if (pf) load_stage((ck + 2) * 64, (ck + 2) % 3);

        int st = ck % 3;
        uint32_t stb = sbase + (uint32_t)st * STAGE_BYTES;
        #pragma unroll
        for (int ks = 0; ks < 4; ks++) {
            int cb = ks * 2 + cpart;                // chunk index 0..7
            uint32_t a[2][4];
            #pragma unroll
            for (int mt = 0; mt < 2; mt++) {
                int r = arow + mt * 16;
                ldsm4(a[mt], stb + swz8(r, cb));
            }
            #pragma unroll
            for (int nt = 0; nt < 4; nt++) {
                uint32_t bf[4];
                int r = brow + nt * 16;
                ldsm4(bf, stb + ARR_BYTES + swz8(r, cb));
                #pragma unroll
                for (int mt = 0; mt < 2; mt++)
                    #pragma unroll
                    for (int jj = 0; jj < 2; jj++)
                        mma16816(acc[mt][nt * 2 + jj], a[mt], bf[jj], bf[jj + 2]);
            }
        }
        if (pf) asm volatile("cp.async.wait_group 1;" ::: "memory"); // ck+1 ready
        else    asm volatile("cp.async.wait_group 0;" ::: "memory");
        __syncthreads();
    }

    // ---- epilogue: transform, direct store, SMEM-transpose mirror ----
    size_t cbo = (size_t)b * NN * NN;
    float* trans = reinterpret_cast<float*>(smem);     // 128 x (stride 132) f32

    #pragma unroll
    for (int mt = 0; mt < 2; mt++)
        #pragma unroll
        for (int j = 0; j < 8; j++)
            #pragma unroll
            for (int rh = 0; rh < 2; rh++) {
                float x0 = acc[mt][j][rh * 2], x1 = acc[mt][j][rh * 2 + 1];
                float v0, v1;
                if (mode0) { v0 = (x0 > 0.0f) ? x0 : 0.0f;
                             v1 = (x1 > 0.0f) ? x1 : 0.0f; }
                else       { v0 = 0.07f * x0 + EPSF;
                             v1 = 0.07f * x1 + EPSF; }
                int gmL = wm * 32 + mt * 16 + (lane >> 2) + rh * 8;
                int gnL = wn * 64 + j * 8 + (lane & 3) * 2;
                float2 v2 = make_float2(v0, v1);
                *reinterpret_cast<float2*>(
                    C + cbo + (size_t)(ti * 128 + gmL) * NN + tj * 128 + gnL) = v2;
                if (ti != tj) {
                    trans[gnL * 132 + gmL] = v0;
                    trans[(gnL + 1) * 132 + gmL] = v1;
                }
            }
    __syncthreads();

    if (ti != tj) {
        #pragma unroll
        for (int i = 0; i < 16; i++) {
            int flat = tid + i * 256;               // 4096 float4s
            int r = flat >> 5, c4 = flat & 31;
            const float* tr = trans + r * 132 + c4 * 4;
            float4 v = make_float4(tr[0], tr[1], tr[2], tr[3]);
            *reinterpret_cast<float4*>(
                C + cbo + (size_t)(tj * 128 + r) * NN + ti * 128 + c4 * 4) = v;
        }
    }
}

// ---------------------------------------------------------------------------
// Kernel 3: per-row: y=l2norm(Y); u=l2norm(|0.5*SW+sqrt(y)|+EPS); out *= u
// ---------------------------------------------------------------------------
__global__ void __launch_bounds__(256) final_kernel(float* __restrict__ out)
{
    int row = blockIdx.x;
    int tid = threadIdx.x;
    const float* yrow = g_Y + (size_t)row * NN;
    const __half* hrow = g_SWf + (size_t)row * NN;
    float* orow = out + (size_t)row * NN;

    __shared__ float red[8];

    float yv[4];
    float s1 = 0.0f;
    #pragma unroll
    for (int j = 0; j < 4; j++) {
        float y = yrow[tid + j * 256];
        yv[j] = y;
        s1 += y * y;
    }
    #pragma unroll
    for (int o = 16; o > 0; o >>= 1) s1 += __shfl_xor_sync(0xffffffffu, s1, o);
    if ((tid & 31) == 0) red[tid >> 5] = s1;
    __syncthreads();
    float yt = 0.0f;
    #pragma unroll
    for (int w = 0; w < 8; w++) yt += red[w];
    float yin = 1.0f / fmaxf(sqrtf(yt), 1e-12f);
    __syncthreads();

    float tv[4];
    float s2 = 0.0f;
    #pragma unroll
    for (int j = 0; j < 4; j++) {
        int m = tid + j * 256;
        float sw = __half2float(hrow[m]);
        float t = fabsf(0.5f * sw + sqrtf(yv[j] * yin)) + EPSF;
        tv[j] = t;
        s2 += t * t;
    }
    #pragma unroll
    for (int o = 16; o > 0; o >>= 1) s2 += __shfl_xor_sync(0xffffffffu, s2, o);
    if ((tid & 31) == 0) red[tid >> 5] = s2;
    __syncthreads();
    float tt = 0.0f;
    #pragma unroll
    for (int w = 0; w < 8; w++) tt += red[w];
    float tin = 1.0f / fmaxf(sqrtf(tt), 1e-12f);

    #pragma unroll
    for (int j = 0; j < 4; j++) {
        int m = tid + j * 256;
        orow[m] = orow[m] * (tv[j] * tin);
    }
}

// ---------------------------------------------------------------------------
extern "C" void kernel_launch(void* const* d_in, const int* in_sizes, int n_in,
                              void* d_out, int out_size)
{
    const float* context     = (const float*)d_in[0];  // (8,1024,128)
    const float* acc_u       = (const float*)d_in[1];
    const float* acc_v       = (const float*)d_in[2];
    const float* uv_angle    = (const float*)d_in[3];
    const float* uv_angleACC = (const float*)d_in[4];
    const float* speed       = (const float*)d_in[5];
    // d_in[6] = isPhy (unused)
    const float* dist        = (const float*)d_in[7];  // (1024,1024)
    const float* angle       = (const float*)d_in[8];  // (1024,1024)
    const float* weight      = (const float*)d_in[9];  // (16,128)
    float* out = (float*)d_out;                        // (8,1024,1024)

    cudaFuncSetAttribute((const void*)&syrk_mma_kernel,
                         cudaFuncAttributeMaxDynamicSharedMemorySize, SYRK_SMEM);

    prep_kernel<<<1024 + NB * NN, 256>>>(context, weight, acc_u, acc_v,
                                         uv_angle, uv_angleACC, speed, dist, angle);
    syrk_mma_kernel<<<2 * NB * NPAIRS, 256, SYRK_SMEM>>>(out);
    final_kernel<<<NB * NN, 256>>>(out);
}

// round 11
// speedup vs baseline: 2.1948x; 1.0082x over previous
#include <cuda_runtime.h>
#include <cuda_bf16.h>
#include <cuda_fp16.h>
#include <math.h>
#include <stdint.h>

#define NB 8
#define NN 1024
#define ND 128
#define NP 16
#define KA 2048           // P*D joint contraction dim for attention
#define EPSF 1e-5f
#define NPAIRS 36         // 8*9/2 symmetric tile pairs

// ---------------------------------------------------------------------------
// Scratch (module-load allocated; no runtime allocation)
// ---------------------------------------------------------------------------
__device__ __align__(16) __half g_A [(size_t)NB * NN * KA];   // 33.5 MB fp16
__device__ __align__(16) __half g_SWf[(size_t)NB * NN * NN];  // 16.8 MB fp16
__device__ __align__(16) float  g_Y [(size_t)NB * NN * NN];   // 33.5 MB fp32

__device__ __forceinline__ uint32_t smem_u32(const void* p) {
    uint32_t a;
    asm("{ .reg .u64 t; cvta.to.shared.u64 t, %1; cvt.u32.u64 %0, t; }"
        : "=r"(a) : "l"(p));
    return a;
}

__device__ __forceinline__ uint32_t pack_h2(float a, float b) {
    __half2 h = __floats2half2_rn(a, b);
    return *reinterpret_cast<uint32_t*>(&h);
}

__device__ __forceinline__ void ldsm4(uint32_t* r, uint32_t addr) {
    asm volatile("ldmatrix.sync.aligned.m8n8.x4.shared.b16 {%0,%1,%2,%3}, [%4];"
                 : "=r"(r[0]), "=r"(r[1]), "=r"(r[2]), "=r"(r[3]) : "r"(addr));
}

__device__ __forceinline__ void mma16816(float* c, const uint32_t* a,
                                         uint32_t b0, uint32_t b1) {
    asm volatile(
        "mma.sync.aligned.m16n8k16.row.col.f32.f16.f16.f32 "
        "{%0,%1,%2,%3}, {%4,%5,%6,%7}, {%8,%9}, {%0,%1,%2,%3};"
        : "+f"(c[0]), "+f"(c[1]), "+f"(c[2]), "+f"(c[3])
        : "r"(a[0]), "r"(a[1]), "r"(a[2]), "r"(a[3]), "r"(b0), "r"(b1));
}

// Swizzled SMEM offset inside one 128-row x 128-byte fp16 array:
// 16B chunk c (0..7) of row stored at slot c ^ (row & 7).
__device__ __forceinline__ uint32_t swz8(int row, int c) {
    return (uint32_t)(row * 128 + ((c ^ (row & 7)) << 4));
}

// ---------------------------------------------------------------------------
// Kernel 1 (merged prep):
//   blocks [0,1024):    build_A — fp16 normalized ctx*w features
//   blocks [1024,2048): selfwind for ONE n across ALL batches —
//     angle/dist row read once; cos(a-uva_b) via addition formula.
// ---------------------------------------------------------------------------
__global__ void __launch_bounds__(256) prep_kernel(
    const float* __restrict__ context, const float* __restrict__ weight,
    const float* __restrict__ acc_u, const float* __restrict__ acc_v,
    const float* __restrict__ uv_angle, const float* __restrict__ uv_angleACC,
    const float* __restrict__ speed,
    const float* __restrict__ dist, const float* __restrict__ angle)
{
    int tid = threadIdx.x;
    if (blockIdx.x < 1024) {
        __shared__ float wsh[NP * ND];
        #pragma unroll
        for (int i = tid; i < NP * ND; i += 256) wsh[i] = weight[i];
        __syncthreads();

        int warp = tid >> 5, lane = tid & 31;
        int row = blockIdx.x * 8 + warp;
        const float4* ctx4 = reinterpret_cast<const float4*>(context + (size_t)row * ND);
        float4 c = ctx4[lane];
        const float4* w4 = reinterpret_cast<const float4*>(wsh);
        uint2* A2 = reinterpret_cast<uint2*>(g_A + (size_t)row * KA);

        #pragma unroll
        for (int p = 0; p < NP; p++) {
            float4 wv = w4[p * 32 + lane];
            float4 pr;
            pr.x = c.x * wv.x; pr.y = c.y * wv.y; pr.z = c.z * wv.z; pr.w = c.w * wv.w;
            float s = pr.x * pr.x + pr.y * pr.y + pr.z * pr.z + pr.w * pr.w;
            #pragma unroll
            for (int o = 16; o > 0; o >>= 1) s += __shfl_xor_sync(0xffffffffu, s, o);
            float inv = 0.25f / fmaxf(sqrtf(s), 1e-12f);   // 0.25 = 1/sqrt(P)
            uint2 hv;
            hv.x = pack_h2(pr.x * inv, pr.y * inv);
            hv.y = pack_h2(pr.z * inv, pr.w * inv);
            A2[p * 32 + lane] = hv;
        }
    } else {
        // ---- selfwind: one n, all 8 batches ----
        int n = blockIdx.x - 1024;

        float cosa[4], sina[4], rd[4];
        #pragma unroll
        for (int j = 0; j < 4; j++) {
            int m = tid + j * 256;
            float a = angle[n * NN + m];
            float dd = dist[n * NN + m] + EPSF;
            __sincosf(a, &sina[j], &cosa[j]);
            rd[j] = __fdividef(1.0f, dd);
        }

        float vals[NB][4];
        __shared__ float redsm[NB * 8];
        #pragma unroll
        for (int b = 0; b < NB; b++) {
            int row = b * NN + n;
            float uva = uv_angle[row];
            float su, cu;
            __sincosf(uva, &su, &cu);
            float au = acc_u[row], av = acc_v[row];
            float tacc = sqrtf(au * au + av * av + EPSF)
                       * fabsf(__cosf(uv_angleACC[row] - uva));
            float spd = fabsf(speed[row]);

            float s = 0.0f;
            #pragma unroll
            for (int j = 0; j < 4; j++) {
                int m = tid + j * 256;
                float cdiff = cosa[j] * cu + sina[j] * su;   // cos(a - uva)
                if (m == n) cdiff += 0.5f * tacc;            // sigma = 0.5 diag
                float v = spd * fabsf(cdiff) * rd[j];
                vals[b][j] = v;
                s += v * v;
            }
            #pragma unroll
            for (int o = 16; o > 0; o >>= 1) s += __shfl_xor_sync(0xffffffffu, s, o);
            if ((tid & 31) == 0) redsm[b * 8 + (tid >> 5)] = s;
        }
        __syncthreads();

        #pragma unroll
        for (int b = 0; b < NB; b++) {
            float tot = 0.0f;
            #pragma unroll
            for (int w = 0; w < 8; w++) tot += redsm[b * 8 + w];
            float inv = rsqrtf(fmaxf(tot, 1e-24f));
            __half* hrow = g_SWf + ((size_t)b * NN + n) * NN;
            #pragma unroll
            for (int j = 0; j < 4; j++) {
                int m = tid + j * 256;
                hrow[m] = __float2half_rn(vals[b][j] * inv);
            }
        }
    }
}

// ---------------------------------------------------------------------------
// Kernel 2 (merged SYRK, single-pass fp16, fp32 accumulate):
//   blocks [0,288):   C = relu(A A^T), K=2048 -> d_out
//   blocks [288,576): C = 0.07*(SW SW^T) + EPS, K=1024 -> g_Y
// 128x128 tile/CTA, 8 warps (32x64), BK=64, 3-stage cp.async pipeline,
// one __syncthreads per chunk, 2 CTAs/SM.
// ---------------------------------------------------------------------------
#define ARR_BYTES 16384                 // 128 rows * 128 B (64 fp16)
#define STAGE_BYTES (2 * ARR_BYTES)     // A, B = 32768
#define SYRK_SMEM (3 * STAGE_BYTES)     // 98304 (covers 67.6KB epilogue too)

__global__ void __launch_bounds__(256, 2) syrk_mma_kernel(float* __restrict__ Cout)
{
    const bool mode0 = blockIdx.x < (NB * NPAIRS);
    const int bpair = mode0 ? blockIdx.x : blockIdx.x - NB * NPAIRS;
    const int K = mode0 ? KA : NN;
    const __half* __restrict__ X = mode0 ? g_A : g_SWf;
    float* __restrict__ C = mode0 ? Cout : g_Y;

    extern __shared__ char smem[];
    const uint32_t sbase = smem_u32(smem);
    const int tid = threadIdx.x;
    const int wid = tid >> 5, lane = tid & 31;
    const int wm = wid & 3, wn = wid >> 2;         // warp tile: rows wm*32, cols wn*64

    int pair = bpair % NPAIRS;
    int b = bpair / NPAIRS;
    int ti = 0;
    while (pair >= ti + 1) { pair -= (ti + 1); ti++; }
    int tj = pair;                                  // tj <= ti

    const __half* pA = X + ((size_t)b * NN + ti * 128) * K;
    const __half* pB = X + ((size_t)b * NN + tj * 128) * K;

    const int NC = K / 64;

    // ---- async load of one 64-wide K slab (A + B) into stage `st` ----
    auto load_stage = [&](int kt, int st) {
        uint32_t stb = sbase + (uint32_t)st * STAGE_BYTES;
        const __half* srcs[2] = { pA, pB };
        #pragma unroll
        for (int arr = 0; arr < 2; arr++) {
            #pragma unroll
            for (int i = 0; i < 4; i++) {
                int g = i * 256 + tid;              // 0..1023 chunk id
                int row = g >> 3, c = g & 7;
                const void* src = srcs[arr] + (size_t)row * K + kt + c * 8;
                uint32_t dst = stb + (uint32_t)arr * ARR_BYTES + swz8(row, c);
                asm volatile("cp.async.cg.shared.global [%0], [%1], 16;"
                             :: "r"(dst), "l"(src));
            }
        }
        asm volatile("cp.async.commit_group;" ::: "memory");
    };

    float acc[2][8][4];
    #pragma unroll
    for (int mt = 0; mt < 2; mt++)
        #pragma unroll
        for (int j = 0; j < 8; j++)
            #pragma unroll
            for (int e = 0; e < 4; e++) acc[mt][j][e] = 0.0f;

    load_stage(0, 0);
    load_stage(64, 1);
    asm volatile("cp.async.wait_group 1;" ::: "memory");   // stage 0 ready
    __syncthreads();

    const int arow = wm * 32 + (lane & 15);
    const int brow = wn * 64 + (lane & 15);
    const int cpart = lane >> 4;                    // 16B half within K16

    for (int ck = 0; ck < NC; ck++) {
        // Prefetch stage ck+2 (buffer (ck+2)%3 last read in iter ck-1,
        // ordered by that iteration's barrier) — overlaps MMAs below.
        bool pf = (ck + 2 < NC);
        if (pf) load_stage((ck + 2) * 64, (ck + 2) % 3);

        int st = ck % 3;
        uint32_t stb = sbase + (uint32_t)st * STAGE_BYTES;
        #pragma unroll
        for (int ks = 0; ks < 4; ks++) {
            int cb = ks * 2 + cpart;                // chunk index 0..7
            uint32_t a[2][4];
            #pragma unroll
            for (int mt = 0; mt < 2; mt++) {
                int r = arow + mt * 16;
                ldsm4(a[mt], stb + swz8(r, cb));
            }
            #pragma unroll
            for (int nt = 0; nt < 4; nt++) {
                uint32_t bf[4];
                int r = brow + nt * 16;
                ldsm4(bf, stb + ARR_BYTES + swz8(r, cb));
                #pragma unroll
                for (int mt = 0; mt < 2; mt++)
                    #pragma unroll
                    for (int jj = 0; jj < 2; jj++)
                        mma16816(acc[mt][nt * 2 + jj], a[mt], bf[jj], bf[jj + 2]);
            }
        }
        if (pf) asm volatile("cp.async.wait_group 1;" ::: "memory"); // ck+1 ready
        else    asm volatile("cp.async.wait_group 0;" ::: "memory");
        __syncthreads();
    }

    // ---- epilogue: transform, direct store, SMEM-transpose mirror ----
    size_t cbo = (size_t)b * NN * NN;
    float* trans = reinterpret_cast<float*>(smem);     // 128 x (stride 132) f32

    #pragma unroll
    for (int mt = 0; mt < 2; mt++)
        #pragma unroll
        for (int j = 0; j < 8; j++)
            #pragma unroll
            for (int rh = 0; rh < 2; rh++) {
                float x0 = acc[mt][j][rh * 2], x1 = acc[mt][j][rh * 2 + 1];
                float v0, v1;
                if (mode0) { v0 = (x0 > 0.0f) ? x0 : 0.0f;
                             v1 = (x1 > 0.0f) ? x1 : 0.0f; }
                else       { v0 = 0.07f * x0 + EPSF;
                             v1 = 0.07f * x1 + EPSF; }
                int gmL = wm * 32 + mt * 16 + (lane >> 2) + rh * 8;
                int gnL = wn * 64 + j * 8 + (lane & 3) * 2;
                float2 v2 = make_float2(v0, v1);
                *reinterpret_cast<float2*>(
                    C + cbo + (size_t)(ti * 128 + gmL) * NN + tj * 128 + gnL) = v2;
                if (ti != tj) {
                    trans[gnL * 132 + gmL] = v0;
                    trans[(gnL + 1) * 132 + gmL] = v1;
                }
            }
    __syncthreads();

    if (ti != tj) {
        #pragma unroll
        for (int i = 0; i < 16; i++) {
            int flat = tid + i * 256;               // 4096 float4s
            int r = flat >> 5, c4 = flat & 31;
            const float* tr = trans + r * 132 + c4 * 4;
            float4 v = make_float4(tr[0], tr[1], tr[2], tr[3]);
            *reinterpret_cast<float4*>(
                C + cbo + (size_t)(tj * 128 + r) * NN + ti * 128 + c4 * 4) = v;
        }
    }
}

// ---------------------------------------------------------------------------
// Kernel 3: per-row: y=l2norm(Y); u=l2norm(|0.5*SW+sqrt(y)|+EPS); out *= u
// ---------------------------------------------------------------------------
__global__ void __launch_bounds__(256) final_kernel(float* __restrict__ out)
{
    int row = blockIdx.x;
    int tid = threadIdx.x;
    const float* yrow = g_Y + (size_t)row * NN;
    const __half* hrow = g_SWf + (size_t)row * NN;
    float* orow = out + (size_t)row * NN;

    __shared__ float red[8];

    float yv[4];
    float s1 = 0.0f;
    #pragma unroll
    for (int j = 0; j < 4; j++) {
        float y = yrow[tid + j * 256];
        yv[j] = y;
        s1 += y * y;
    }
    #pragma unroll
    for (int o = 16; o > 0; o >>= 1) s1 += __shfl_xor_sync(0xffffffffu, s1, o);
    if ((tid & 31) == 0) red[tid >> 5] = s1;
    __syncthreads();
    float yt = 0.0f;
    #pragma unroll
    for (int w = 0; w < 8; w++) yt += red[w];
    float yin = 1.0f / fmaxf(sqrtf(yt), 1e-12f);
    __syncthreads();

    float tv[4];
    float s2 = 0.0f;
    #pragma unroll
    for (int j = 0; j < 4; j++) {
        int m = tid + j * 256;
        float sw = __half2float(hrow[m]);
        float t = fabsf(0.5f * sw + sqrtf(yv[j] * yin)) + EPSF;
        tv[j] = t;
        s2 += t * t;
    }
    #pragma unroll
    for (int o = 16; o > 0; o >>= 1) s2 += __shfl_xor_sync(0xffffffffu, s2, o);
    if ((tid & 31) == 0) red[tid >> 5] = s2;
    __syncthreads();
    float tt = 0.0f;
    #pragma unroll
    for (int w = 0; w < 8; w++) tt += red[w];
    float tin = 1.0f / fmaxf(sqrtf(tt), 1e-12f);

    #pragma unroll
    for (int j = 0; j < 4; j++) {
        int m = tid + j * 256;
        orow[m] = orow[m] * (tv[j] * tin);
    }
}

// ---------------------------------------------------------------------------
extern "C" void kernel_launch(void* const* d_in, const int* in_sizes, int n_in,
                              void* d_out, int out_size)
{
    const float* context     = (const float*)d_in[0];  // (8,1024,128)
    const float* acc_u       = (const float*)d_in[1];
    const float* acc_v       = (const float*)d_in[2];
    const float* uv_angle    = (const float*)d_in[3];
    const float* uv_angleACC = (const float*)d_in[4];
    const float* speed       = (const float*)d_in[5];
    // d_in[6] = isPhy (unused)
    const float* dist        = (const float*)d_in[7];  // (1024,1024)
    const float* angle       = (const float*)d_in[8];  // (1024,1024)
    const float* weight      = (const float*)d_in[9];  // (16,128)
    float* out = (float*)d_out;                        // (8,1024,1024)

    cudaFuncSetAttribute((const void*)&syrk_mma_kernel,
                         cudaFuncAttributeMaxDynamicSharedMemorySize, SYRK_SMEM);

    prep_kernel<<<2048, 256>>>(context, weight, acc_u, acc_v,
                               uv_angle, uv_angleACC, speed, dist, angle);
    syrk_mma_kernel<<<2 * NB * NPAIRS, 256, SYRK_SMEM>>>(out);
    final_kernel<<<NB * NN, 256>>>(out);
}

// round 12
// speedup vs baseline: 2.4009x; 1.0939x over previous
#include <cuda_runtime.h>
#include <cuda_bf16.h>
#include <cuda_fp16.h>
#include <math.h>
#include <stdint.h>

#define NB 8
#define NN 1024
#define ND 128
#define NP 16
#define KA 2048           // P*D joint contraction dim for attention
#define EPSF 1e-5f
#define NPAIRS 36         // 8*9/2 symmetric tile pairs

// ---------------------------------------------------------------------------
// Scratch (module-load allocated; no runtime allocation)
// ---------------------------------------------------------------------------
__device__ __align__(16) __half g_A  [(size_t)NB * NN * KA];  // 33.5 MB fp16
__device__ __align__(16) __half g_SWf[(size_t)NB * NN * NN];  // 16.8 MB fp16
__device__ __align__(16) __half g_Yh [(size_t)NB * NN * NN];  // 16.8 MB fp16

__device__ __forceinline__ uint32_t smem_u32(const void* p) {
    uint32_t a;
    asm("{ .reg .u64 t; cvta.to.shared.u64 t, %1; cvt.u32.u64 %0, t; }"
        : "=r"(a) : "l"(p));
    return a;
}

__device__ __forceinline__ uint32_t pack_h2(float a, float b) {
    __half2 h = __floats2half2_rn(a, b);
    return *reinterpret_cast<uint32_t*>(&h);
}

__device__ __forceinline__ void ldsm4(uint32_t* r, uint32_t addr) {
    asm volatile("ldmatrix.sync.aligned.m8n8.x4.shared.b16 {%0,%1,%2,%3}, [%4];"
                 : "=r"(r[0]), "=r"(r[1]), "=r"(r[2]), "=r"(r[3]) : "r"(addr));
}

__device__ __forceinline__ void mma16816(float* c, const uint32_t* a,
                                         uint32_t b0, uint32_t b1) {
    asm volatile(
        "mma.sync.aligned.m16n8k16.row.col.f32.f16.f16.f32 "
        "{%0,%1,%2,%3}, {%4,%5,%6,%7}, {%8,%9}, {%0,%1,%2,%3};"
        : "+f"(c[0]), "+f"(c[1]), "+f"(c[2]), "+f"(c[3])
        : "r"(a[0]), "r"(a[1]), "r"(a[2]), "r"(a[3]), "r"(b0), "r"(b1));
}

// Swizzled SMEM offset inside one 128-row x 128-byte fp16 array:
// 16B chunk c (0..7) of row stored at slot c ^ (row & 7).
__device__ __forceinline__ uint32_t swz8(int row, int c) {
    return (uint32_t)(row * 128 + ((c ^ (row & 7)) << 4));
}

// ---------------------------------------------------------------------------
// Kernel 1 (merged prep):
//   blocks [0,1024):    build_A — fp16 normalized ctx*w features
//   blocks [1024,2048): selfwind for ONE n across ALL batches.
//   Two-pass: pass1 row sums (no vals array), pass2 recompute + write.
// ---------------------------------------------------------------------------
__global__ void __launch_bounds__(256) prep_kernel(
    const float* __restrict__ context, const float* __restrict__ weight,
    const float* __restrict__ acc_u, const float* __restrict__ acc_v,
    const float* __restrict__ uv_angle, const float* __restrict__ uv_angleACC,
    const float* __restrict__ speed,
    const float* __restrict__ dist, const float* __restrict__ angle)
{
    int tid = threadIdx.x;
    if (blockIdx.x < 1024) {
        __shared__ float wsh[NP * ND];
        #pragma unroll
        for (int i = tid; i < NP * ND; i += 256) wsh[i] = weight[i];
        __syncthreads();

        int warp = tid >> 5, lane = tid & 31;
        int row = blockIdx.x * 8 + warp;
        const float4* ctx4 = reinterpret_cast<const float4*>(context + (size_t)row * ND);
        float4 c = ctx4[lane];
        const float4* w4 = reinterpret_cast<const float4*>(wsh);
        uint2* A2 = reinterpret_cast<uint2*>(g_A + (size_t)row * KA);

        #pragma unroll
        for (int p = 0; p < NP; p++) {
            float4 wv = w4[p * 32 + lane];
            float4 pr;
            pr.x = c.x * wv.x; pr.y = c.y * wv.y; pr.z = c.z * wv.z; pr.w = c.w * wv.w;
            float s = pr.x * pr.x + pr.y * pr.y + pr.z * pr.z + pr.w * pr.w;
            #pragma unroll
            for (int o = 16; o > 0; o >>= 1) s += __shfl_xor_sync(0xffffffffu, s, o);
            float inv = 0.25f / fmaxf(sqrtf(s), 1e-12f);   // 0.25 = 1/sqrt(P)
            uint2 hv;
            hv.x = pack_h2(pr.x * inv, pr.y * inv);
            hv.y = pack_h2(pr.z * inv, pr.w * inv);
            A2[p * 32 + lane] = hv;
        }
    } else {
        // ---- selfwind: one n, all 8 batches, two passes ----
        int n = blockIdx.x - 1024;

        float cosa[4], sina[4], rd[4];
        #pragma unroll
        for (int j = 0; j < 4; j++) {
            int m = tid + j * 256;
            float a = angle[n * NN + m];
            float dd = dist[n * NN + m] + EPSF;
            __sincosf(a, &sina[j], &cosa[j]);
            rd[j] = __fdividef(1.0f, dd);
        }

        __shared__ float redsm[NB * 8];
        // pass 1: row sums
        #pragma unroll
        for (int b = 0; b < NB; b++) {
            int row = b * NN + n;
            float uva = uv_angle[row];
            float su, cu;
            __sincosf(uva, &su, &cu);
            float au = acc_u[row], av = acc_v[row];
            float tacc = sqrtf(au * au + av * av + EPSF)
                       * fabsf(__cosf(uv_angleACC[row] - uva));
            float spd = fabsf(speed[row]);

            float s = 0.0f;
            #pragma unroll
            for (int j = 0; j < 4; j++) {
                int m = tid + j * 256;
                float cdiff = cosa[j] * cu + sina[j] * su;   // cos(a - uva)
                if (m == n) cdiff += 0.5f * tacc;            // sigma = 0.5 diag
                float v = spd * fabsf(cdiff) * rd[j];
                s += v * v;
            }
            #pragma unroll
            for (int o = 16; o > 0; o >>= 1) s += __shfl_xor_sync(0xffffffffu, s, o);
            if ((tid & 31) == 0) redsm[b * 8 + (tid >> 5)] = s;
        }
        __syncthreads();

        // pass 2: recompute v (bitwise identical) and write normalized fp16
        #pragma unroll
        for (int b = 0; b < NB; b++) {
            int row = b * NN + n;
            float uva = uv_angle[row];
            float su, cu;
            __sincosf(uva, &su, &cu);
            float au = acc_u[row], av = acc_v[row];
            float tacc = sqrtf(au * au + av * av + EPSF)
                       * fabsf(__cosf(uv_angleACC[row] - uva));
            float spd = fabsf(speed[row]);

            float tot = 0.0f;
            #pragma unroll
            for (int w = 0; w < 8; w++) tot += redsm[b * 8 + w];
            float inv = rsqrtf(fmaxf(tot, 1e-24f));

            __half* hrow = g_SWf + ((size_t)b * NN + n) * NN;
            #pragma unroll
            for (int j = 0; j < 4; j++) {
                int m = tid + j * 256;
                float cdiff = cosa[j] * cu + sina[j] * su;
                if (m == n) cdiff += 0.5f * tacc;
                float v = spd * fabsf(cdiff) * rd[j];
                hrow[m] = __float2half_rn(v * inv);
            }
        }
    }
}

// ---------------------------------------------------------------------------
// Kernel 2 (merged SYRK, single-pass fp16, fp32 accumulate):
//   blocks [0,288):   C = relu(A A^T), K=2048 -> d_out (fp32)
//   blocks [288,576): C = 0.07*(SW SW^T) + EPS, K=1024 -> g_Yh (fp16)
// 128x128 tile/CTA, 8 warps (32x64), BK=64, 3-stage cp.async pipeline,
// one __syncthreads per chunk, 2 CTAs/SM.
// ---------------------------------------------------------------------------
#define ARR_BYTES 16384                 // 128 rows * 128 B (64 fp16)
#define STAGE_BYTES (2 * ARR_BYTES)     // A, B = 32768
#define SYRK_SMEM (3 * STAGE_BYTES)     // 98304 (covers 67.6KB epilogue too)

__global__ void __launch_bounds__(256, 2) syrk_mma_kernel(float* __restrict__ Cout)
{
    const bool mode0 = blockIdx.x < (NB * NPAIRS);
    const int bpair = mode0 ? blockIdx.x : blockIdx.x - NB * NPAIRS;
    const int K = mode0 ? KA : NN;
    const __half* __restrict__ X = mode0 ? g_A : g_SWf;

    extern __shared__ char smem[];
    const uint32_t sbase = smem_u32(smem);
    const int tid = threadIdx.x;
    const int wid = tid >> 5, lane = tid & 31;
    const int wm = wid & 3, wn = wid >> 2;         // warp tile: rows wm*32, cols wn*64

    int pair = bpair % NPAIRS;
    int b = bpair / NPAIRS;
    int ti = 0;
    while (pair >= ti + 1) { pair -= (ti + 1); ti++; }
    int tj = pair;                                  // tj <= ti

    const __half* pA = X + ((size_t)b * NN + ti * 128) * K;
    const __half* pB = X + ((size_t)b * NN + tj * 128) * K;

    const int NC = K / 64;

    // ---- async load of one 64-wide K slab (A + B) into stage `st` ----
    auto load_stage = [&](int kt, int st) {
        uint32_t stb = sbase + (uint32_t)st * STAGE_BYTES;
        const __half* srcs[2] = { pA, pB };
        #pragma unroll
        for (int arr = 0; arr < 2; arr++) {
            #pragma unroll
            for (int i = 0; i < 4; i++) {
                int g = i * 256 + tid;              // 0..1023 chunk id
                int row = g >> 3, c = g & 7;
                const void* src = srcs[arr] + (size_t)row * K + kt + c * 8;
                uint32_t dst = stb + (uint32_t)arr * ARR_BYTES + swz8(row, c);
                asm volatile("cp.async.cg.shared.global [%0], [%1], 16;"
                             :: "r"(dst), "l"(src));
            }
        }
        asm volatile("cp.async.commit_group;" ::: "memory");
    };

    float acc[2][8][4];
    #pragma unroll
    for (int mt = 0; mt < 2; mt++)
        #pragma unroll
        for (int j = 0; j < 8; j++)
            #pragma unroll
            for (int e = 0; e < 4; e++) acc[mt][j][e] = 0.0f;

    load_stage(0, 0);
    load_stage(64, 1);
    asm volatile("cp.async.wait_group 1;" ::: "memory");   // stage 0 ready
    __syncthreads();

    const int arow = wm * 32 + (lane & 15);
    const int brow = wn * 64 + (lane & 15);
    const int cpart = lane >> 4;                    // 16B half within K16

    for (int ck = 0; ck < NC; ck++) {
        // Prefetch stage ck+2 (buffer (ck+2)%3 last read in iter ck-1,
        // ordered by that iteration's barrier) — overlaps MMAs below.
        bool pf = (ck + 2 < NC);
        if (pf) load_stage((ck + 2) * 64, (ck + 2) % 3);

        int st = ck % 3;
        uint32_t stb = sbase + (uint32_t)st * STAGE_BYTES;
        #pragma unroll
        for (int ks = 0; ks < 4; ks++) {
            int cb = ks * 2 + cpart;                // chunk index 0..7
            uint32_t a[2][4];
            #pragma unroll
            for (int mt = 0; mt < 2; mt++) {
                int r = arow + mt * 16;
                ldsm4(a[mt], stb + swz8(r, cb));
            }
            #pragma unroll
            for (int nt = 0; nt < 4; nt++) {
                uint32_t bf[4];
                int r = brow + nt * 16;
                ldsm4(bf, stb + ARR_BYTES + swz8(r, cb));
                #pragma unroll
                for (int mt = 0; mt < 2; mt++)
                    #pragma unroll
                    for (int jj = 0; jj < 2; jj++)
                        mma16816(acc[mt][nt * 2 + jj], a[mt], bf[jj], bf[jj + 2]);
            }
        }
        if (pf) asm volatile("cp.async.wait_group 1;" ::: "memory"); // ck+1 ready
        else    asm volatile("cp.async.wait_group 0;" ::: "memory");
        __syncthreads();
    }

    // ---- epilogue ----
    float* trans = reinterpret_cast<float*>(smem);     // 128 x (stride 132) f32

    if (mode0) {
        size_t cbo = (size_t)b * NN * NN;
        #pragma unroll
        for (int mt = 0; mt < 2; mt++)
            #pragma unroll
            for (int j = 0; j < 8; j++)
                #pragma unroll
                for (int rh = 0; rh < 2; rh++) {
                    float x0 = acc[mt][j][rh * 2], x1 = acc[mt][j][rh * 2 + 1];
                    float v0 = (x0 > 0.0f) ? x0 : 0.0f;
                    float v1 = (x1 > 0.0f) ? x1 : 0.0f;
                    int gmL = wm * 32 + mt * 16 + (lane >> 2) + rh * 8;
                    int gnL = wn * 64 + j * 8 + (lane & 3) * 2;
                    *reinterpret_cast<float2*>(
                        Cout + cbo + (size_t)(ti * 128 + gmL) * NN + tj * 128 + gnL)
                        = make_float2(v0, v1);
                    if (ti != tj) {
                        trans[gnL * 132 + gmL] = v0;
                        trans[(gnL + 1) * 132 + gmL] = v1;
                    }
                }
        __syncthreads();
        if (ti != tj) {
            #pragma unroll
            for (int i = 0; i < 16; i++) {
                int flat = tid + i * 256;
                int r = flat >> 5, c4 = flat & 31;
                const float* tr = trans + r * 132 + c4 * 4;
                float4 v = make_float4(tr[0], tr[1], tr[2], tr[3]);
                *reinterpret_cast<float4*>(
                    Cout + cbo + (size_t)(tj * 128 + r) * NN + ti * 128 + c4 * 4) = v;
            }
        }
    } else {
        __half* Yh = g_Yh + (size_t)b * NN * NN;
        #pragma unroll
        for (int mt = 0; mt < 2; mt++)
            #pragma unroll
            for (int j = 0; j < 8; j++)
                #pragma unroll
                for (int rh = 0; rh < 2; rh++) {
                    float x0 = acc[mt][j][rh * 2], x1 = acc[mt][j][rh * 2 + 1];
                    float v0 = 0.07f * x0 + EPSF;
                    float v1 = 0.07f * x1 + EPSF;
                    int gmL = wm * 32 + mt * 16 + (lane >> 2) + rh * 8;
                    int gnL = wn * 64 + j * 8 + (lane & 3) * 2;
                    __half2 hv = __floats2half2_rn(v0, v1);
                    *reinterpret_cast<__half2*>(
                        Yh + (size_t)(ti * 128 + gmL) * NN + tj * 128 + gnL) = hv;
                    if (ti != tj) {
                        trans[gnL * 132 + gmL] = v0;
                        trans[(gnL + 1) * 132 + gmL] = v1;
                    }
                }
        __syncthreads();
        if (ti != tj) {
            #pragma unroll
            for (int i = 0; i < 16; i++) {
                int flat = tid + i * 256;
                int r = flat >> 5, c4 = flat & 31;
                const float* tr = trans + r * 132 + c4 * 4;
                __half2 h0 = __floats2half2_rn(tr[0], tr[1]);
                __half2 h1 = __floats2half2_rn(tr[2], tr[3]);
                uint2 pk;
                pk.x = *reinterpret_cast<uint32_t*>(&h0);
                pk.y = *reinterpret_cast<uint32_t*>(&h1);
                *reinterpret_cast<uint2*>(
                    Yh + (size_t)(tj * 128 + r) * NN + ti * 128 + c4 * 4) = pk;
            }
        }
    }
}

// ---------------------------------------------------------------------------
// Kernel 3: per-row: y=l2norm(Y); u=l2norm(|0.5*SW+sqrt(y)|+EPS); out *= u
// half2-vectorized loads.
// ---------------------------------------------------------------------------
__global__ void __launch_bounds__(256) final_kernel(float* __restrict__ out)
{
    int row = blockIdx.x;
    int tid = threadIdx.x;
    const __half2* y2 = reinterpret_cast<const __half2*>(g_Yh + (size_t)row * NN);
    const __half2* s2p = reinterpret_cast<const __half2*>(g_SWf + (size_t)row * NN);
    float2* o2 = reinterpret_cast<float2*>(out + (size_t)row * NN);

    __shared__ float red[8];

    float2 yv[2], swv[2];
    float s1 = 0.0f;
    #pragma unroll
    for (int j = 0; j < 2; j++) {
        int m2 = tid + j * 256;
        yv[j] = __half22float2(y2[m2]);
        swv[j] = __half22float2(s2p[m2]);
        s1 += yv[j].x * yv[j].x + yv[j].y * yv[j].y;
    }
    #pragma unroll
    for (int o = 16; o > 0; o >>= 1) s1 += __shfl_xor_sync(0xffffffffu, s1, o);
    if ((tid & 31) == 0) red[tid >> 5] = s1;
    __syncthreads();
    float yt = 0.0f;
    #pragma unroll
    for (int w = 0; w < 8; w++) yt += red[w];
    float yin = rsqrtf(fmaxf(yt, 1e-24f));
    __syncthreads();

    float tv[2][2];
    float s2 = 0.0f;
    #pragma unroll
    for (int j = 0; j < 2; j++) {
        float t0 = fabsf(0.5f * swv[j].x + sqrtf(yv[j].x * yin)) + EPSF;
        float t1 = fabsf(0.5f * swv[j].y + sqrtf(yv[j].y * yin)) + EPSF;
        tv[j][0] = t0; tv[j][1] = t1;
        s2 += t0 * t0 + t1 * t1;
    }
    #pragma unroll
    for (int o = 16; o > 0; o >>= 1) s2 += __shfl_xor_sync(0xffffffffu, s2, o);
    if ((tid & 31) == 0) red[tid >> 5] = s2;
    __syncthreads();
    float tt = 0.0f;
    #pragma unroll
    for (int w = 0; w < 8; w++) tt += red[w];
    float tin = rsqrtf(fmaxf(tt, 1e-24f));

    #pragma unroll
    for (int j = 0; j < 2; j++) {
        int m2 = tid + j * 256;
        float2 ov = o2[m2];
        ov.x *= tv[j][0] * tin;
        ov.y *= tv[j][1] * tin;
        o2[m2] = ov;
    }
}

// ---------------------------------------------------------------------------
extern "C" void kernel_launch(void* const* d_in, const int* in_sizes, int n_in,
                              void* d_out, int out_size)
{
    const float* context     = (const float*)d_in[0];  // (8,1024,128)
    const float* acc_u       = (const float*)d_in[1];
    const float* acc_v       = (const float*)d_in[2];
    const float* uv_angle    = (const float*)d_in[3];
    const float* uv_angleACC = (const float*)d_in[4];
    const float* speed       = (const float*)d_in[5];
    // d_in[6] = isPhy (unused)
    const float* dist        = (const float*)d_in[7];  // (1024,1024)
    const float* angle       = (const float*)d_in[8];  // (1024,1024)
    const float* weight      = (const float*)d_in[9];  // (16,128)
    float* out = (float*)d_out;                        // (8,1024,1024)

    cudaFuncSetAttribute((const void*)&syrk_mma_kernel,
                         cudaFuncAttributeMaxDynamicSharedMemorySize, SYRK_SMEM);

    prep_kernel<<<2048, 256>>>(context, weight, acc_u, acc_v,
                               uv_angle, uv_angleACC, speed, dist, angle);
    syrk_mma_kernel<<<2 * NB * NPAIRS, 256, SYRK_SMEM>>>(out);
    final_kernel<<<NB * NN, 256>>>(out);
}

// round 15
// speedup vs baseline: 2.4664x; 1.0273x over previous
#include <cuda_runtime.h>
#include <cuda_bf16.h>
#include <cuda_fp16.h>
#include <math.h>
#include <stdint.h>

#define NB 8
#define NN 1024
#define ND 128
#define NP 16
#define KA 2048           // P*D joint contraction dim for attention
#define EPSF 1e-5f
#define NPAIRS 36         // 8*9/2 symmetric tile pairs

// ---------------------------------------------------------------------------
// Scratch (module-load allocated; no runtime allocation)
// ---------------------------------------------------------------------------
__device__ __align__(16) __half g_A  [(size_t)NB * NN * KA];  // 33.5 MB fp16
__device__ __align__(16) __half g_SWf[(size_t)NB * NN * NN];  // 16.8 MB fp16
__device__ __align__(16) __half g_Yh [(size_t)NB * NN * NN];  // 16.8 MB fp16

__device__ __forceinline__ uint32_t smem_u32(const void* p) {
    uint32_t a;
    asm("{ .reg .u64 t; cvta.to.shared.u64 t, %1; cvt.u32.u64 %0, t; }"
        : "=r"(a) : "l"(p));
    return a;
}

__device__ __forceinline__ uint32_t pack_h2(float a, float b) {
    __half2 h = __floats2half2_rn(a, b);
    return *reinterpret_cast<uint32_t*>(&h);
}

__device__ __forceinline__ void ldsm4(uint32_t* r, uint32_t addr) {
    asm volatile("ldmatrix.sync.aligned.m8n8.x4.shared.b16 {%0,%1,%2,%3}, [%4];"
                 : "=r"(r[0]), "=r"(r[1]), "=r"(r[2]), "=r"(r[3]) : "r"(addr));
}

__device__ __forceinline__ void mma16816(float* c, const uint32_t* a,
                                         uint32_t b0, uint32_t b1) {
    asm volatile(
        "mma.sync.aligned.m16n8k16.row.col.f32.f16.f16.f32 "
        "{%0,%1,%2,%3}, {%4,%5,%6,%7}, {%8,%9}, {%0,%1,%2,%3};"
        : "+f"(c[0]), "+f"(c[1]), "+f"(c[2]), "+f"(c[3])
        : "r"(a[0]), "r"(a[1]), "r"(a[2]), "r"(a[3]), "r"(b0), "r"(b1));
}

// Swizzled SMEM offset inside one 128-row x 128-byte fp16 array:
// 16B chunk c (0..7) of row stored at slot c ^ (row & 7).
__device__ __forceinline__ uint32_t swz8(int row, int c) {
    return (uint32_t)(row * 128 + ((c ^ (row & 7)) << 4));
}

// ---------------------------------------------------------------------------
// Kernel 1 (merged prep):
//   blocks [0,1024):    build_A — fp16 normalized ctx*w features
//   blocks [1024,2048): selfwind for ONE n across ALL batches.
//   Unnormalized v stashed in SMEM (32 KB); single barrier; pass2 scales.
// ---------------------------------------------------------------------------
__global__ void __launch_bounds__(256) prep_kernel(
    const float* __restrict__ context, const float* __restrict__ weight,
    const float* __restrict__ acc_u, const float* __restrict__ acc_v,
    const float* __restrict__ uv_angle, const float* __restrict__ uv_angleACC,
    const float* __restrict__ speed,
    const float* __restrict__ dist, const float* __restrict__ angle)
{
    __shared__ float sv[NB * NN];          // 32 KB (build_A uses first 8 KB)
    __shared__ float redsm[NB * 8];
    int tid = threadIdx.x;

    if (blockIdx.x < 1024) {
        float* wsh = sv;                   // 16*128 floats = 8 KB
        #pragma unroll
        for (int i = tid; i < NP * ND; i += 256) wsh[i] = weight[i];
        __syncthreads();

        int warp = tid >> 5, lane = tid & 31;
        int row = blockIdx.x * 8 + warp;
        const float4* ctx4 = reinterpret_cast<const float4*>(context + (size_t)row * ND);
        float4 c = ctx4[lane];
        const float4* w4 = reinterpret_cast<const float4*>(wsh);
        uint2* A2 = reinterpret_cast<uint2*>(g_A + (size_t)row * KA);

        #pragma unroll
        for (int p = 0; p < NP; p++) {
            float4 wv = w4[p * 32 + lane];
            float4 pr;
            pr.x = c.x * wv.x; pr.y = c.y * wv.y; pr.z = c.z * wv.z; pr.w = c.w * wv.w;
            float s = pr.x * pr.x + pr.y * pr.y + pr.z * pr.z + pr.w * pr.w;
            #pragma unroll
            for (int o = 16; o > 0; o >>= 1) s += __shfl_xor_sync(0xffffffffu, s, o);
            float inv = 0.25f / fmaxf(sqrtf(s), 1e-12f);   // 0.25 = 1/sqrt(P)
            uint2 hv;
            hv.x = pack_h2(pr.x * inv, pr.y * inv);
            hv.y = pack_h2(pr.z * inv, pr.w * inv);
            A2[p * 32 + lane] = hv;
        }
    } else {
        // ---- selfwind: one n, all 8 batches ----
        int n = blockIdx.x - 1024;

        float cosa[4], sina[4], rd[4];
        #pragma unroll
        for (int j = 0; j < 4; j++) {
            int m = tid + j * 256;
            float a = angle[n * NN + m];
            float dd = dist[n * NN + m] + EPSF;
            __sincosf(a, &sina[j], &cosa[j]);
            rd[j] = __fdividef(1.0f, dd);
        }

        // pass 1: compute v once, stash in smem, accumulate row sums
        #pragma unroll
        for (int b = 0; b < NB; b++) {
            int row = b * NN + n;
            float uva = uv_angle[row];
            float su, cu;
            __sincosf(uva, &su, &cu);
            float au = acc_u[row], av = acc_v[row];
            float tacc = sqrtf(au * au + av * av + EPSF)
                       * fabsf(__cosf(uv_angleACC[row] - uva));
            float spd = fabsf(speed[row]);

            float s = 0.0f;
            #pragma unroll
            for (int j = 0; j < 4; j++) {
                int m = tid + j * 256;
                float cdiff = cosa[j] * cu + sina[j] * su;   // cos(a - uva)
                if (m == n) cdiff += 0.5f * tacc;            // sigma = 0.5 diag
                float v = spd * fabsf(cdiff) * rd[j];
                sv[b * NN + m] = v;
                s += v * v;
            }
            #pragma unroll
            for (int o = 16; o > 0; o >>= 1) s += __shfl_xor_sync(0xffffffffu, s, o);
            if ((tid & 31) == 0) redsm[b * 8 + (tid >> 5)] = s;
        }
        __syncthreads();

        // pass 2: scale stashed values, write normalized fp16
        #pragma unroll
        for (int b = 0; b < NB; b++) {
            float tot = 0.0f;
            #pragma unroll
            for (int w = 0; w < 8; w++) tot += redsm[b * 8 + w];
            float inv = rsqrtf(fmaxf(tot, 1e-24f));
            __half* hrow = g_SWf + ((size_t)b * NN + n) * NN;
            #pragma unroll
            for (int j = 0; j < 4; j++) {
                int m = tid + j * 256;
                hrow[m] = __float2half_rn(sv[b * NN + m] * inv);
            }
        }
    }
}

// ---------------------------------------------------------------------------
// Kernel 2 (merged SYRK, single-pass fp16, fp32 accumulate):
//   blocks [0,288):   C = relu(A A^T), K=2048 -> d_out (fp32)
//   blocks [288,576): C = 0.07*(SW SW^T) + EPS, K=1024 -> g_Yh (fp16)
// 128x128 tile/CTA, 8 warps (32x64), BK=64, 3-stage cp.async pipeline,
// one __syncthreads per chunk, 2 CTAs/SM.
// ---------------------------------------------------------------------------
#define ARR_BYTES 16384                 // 128 rows * 128 B (64 fp16)
#define STAGE_BYTES (2 * ARR_BYTES)     // A, B = 32768
#define SYRK_SMEM (3 * STAGE_BYTES)     // 98304 (covers 67.6KB epilogue too)

__global__ void __launch_bounds__(256, 2) syrk_mma_kernel(float* __restrict__ Cout)
{
    const bool mode0 = blockIdx.x < (NB * NPAIRS);
    const int bpair = mode0 ? blockIdx.x : blockIdx.x - NB * NPAIRS;
    const int K = mode0 ? KA : NN;
    const __half* __restrict__ X = mode0 ? g_A : g_SWf;

    extern __shared__ char smem[];
    const uint32_t sbase = smem_u32(smem);
    const int tid = threadIdx.x;
    const int wid = tid >> 5, lane = tid & 31;
    const int wm = wid & 3, wn = wid >> 2;         // warp tile: rows wm*32, cols wn*64

    int pair = bpair % NPAIRS;
    int b = bpair / NPAIRS;
    int ti = 0;
    while (pair >= ti + 1) { pair -= (ti + 1); ti++; }
    int tj = pair;                                  // tj <= ti

    const __half* pA = X + ((size_t)b * NN + ti * 128) * K;
    const __half* pB = X + ((size_t)b * NN + tj * 128) * K;

    const int NC = K / 64;

    // ---- async load of one 64-wide K slab (A + B) into stage `st` ----
    auto load_stage = [&](int kt, int st) {
        uint32_t stb = sbase + (uint32_t)st * STAGE_BYTES;
        const __half* srcs[2] = { pA, pB };
        #pragma unroll
        for (int arr = 0; arr < 2; arr++) {
            #pragma unroll
            for (int i = 0; i < 4; i++) {
                int g = i * 256 + tid;              // 0..1023 chunk id
                int row = g >> 3, c = g & 7;
                const void* src = srcs[arr] + (size_t)row * K + kt + c * 8;
                uint32_t dst = stb + (uint32_t)arr * ARR_BYTES + swz8(row, c);
                asm volatile("cp.async.cg.shared.global [%0], [%1], 16;"
                             :: "r"(dst), "l"(src));
            }
        }
        asm volatile("cp.async.commit_group;" ::: "memory");
    };

    float acc[2][8][4];
    #pragma unroll
    for (int mt = 0; mt < 2; mt++)
        #pragma unroll
        for (int j = 0; j < 8; j++)
            #pragma unroll
            for (int e = 0; e < 4; e++) acc[mt][j][e] = 0.0f;

    load_stage(0, 0);
    load_stage(64, 1);
    asm volatile("cp.async.wait_group 1;" ::: "memory");   // stage 0 ready
    __syncthreads();

    const int arow = wm * 32 + (lane & 15);
    const int brow = wn * 64 + (lane & 15);
    const int cpart = lane >> 4;                    // 16B half within K16

    for (int ck = 0; ck < NC; ck++) {
        // Prefetch stage ck+2 (buffer (ck+2)%3 last read in iter ck-1,
        // ordered by that iteration's barrier) — overlaps MMAs below.
        bool pf = (ck + 2 < NC);
        if (pf) load_stage((ck + 2) * 64, (ck + 2) % 3);

        int st = ck % 3;
        uint32_t stb = sbase + (uint32_t)st * STAGE_BYTES;
        #pragma unroll
        for (int ks = 0; ks < 4; ks++) {
            int cb = ks * 2 + cpart;                // chunk index 0..7
            uint32_t a[2][4];
            #pragma unroll
            for (int mt = 0; mt < 2; mt++) {
                int r = arow + mt * 16;
                ldsm4(a[mt], stb + swz8(r, cb));
            }
            #pragma unroll
            for (int nt = 0; nt < 4; nt++) {
                uint32_t bf[4];
                int r = brow + nt * 16;
                ldsm4(bf, stb + ARR_BYTES + swz8(r, cb));
                #pragma unroll
                for (int mt = 0; mt < 2; mt++)
                    #pragma unroll
                    for (int jj = 0; jj < 2; jj++)
                        mma16816(acc[mt][nt * 2 + jj], a[mt], bf[jj], bf[jj + 2]);
            }
        }
        if (pf) asm volatile("cp.async.wait_group 1;" ::: "memory"); // ck+1 ready
        else    asm volatile("cp.async.wait_group 0;" ::: "memory");
        __syncthreads();
    }

    // ---- epilogue ----
    float* trans = reinterpret_cast<float*>(smem);     // 128 x (stride 132) f32

    if (mode0) {
        size_t cbo = (size_t)b * NN * NN;
        #pragma unroll
        for (int mt = 0; mt < 2; mt++)
            #pragma unroll
            for (int j = 0; j < 8; j++)
                #pragma unroll
                for (int rh = 0; rh < 2; rh++) {
                    float x0 = acc[mt][j][rh * 2], x1 = acc[mt][j][rh * 2 + 1];
                    float v0 = (x0 > 0.0f) ? x0 : 0.0f;
                    float v1 = (x1 > 0.0f) ? x1 : 0.0f;
                    int gmL = wm * 32 + mt * 16 + (lane >> 2) + rh * 8;
                    int gnL = wn * 64 + j * 8 + (lane & 3) * 2;
                    *reinterpret_cast<float2*>(
                        Cout + cbo + (size_t)(ti * 128 + gmL) * NN + tj * 128 + gnL)
                        = make_float2(v0, v1);
                    if (ti != tj) {
                        trans[gnL * 132 + gmL] = v0;
                        trans[(gnL + 1) * 132 + gmL] = v1;
                    }
                }
        __syncthreads();
        if (ti != tj) {
            #pragma unroll
            for (int i = 0; i < 16; i++) {
                int flat = tid + i * 256;
                int r = flat >> 5, c4 = flat & 31;
                const float* tr = trans + r * 132 + c4 * 4;
                float4 v = make_float4(tr[0], tr[1], tr[2], tr[3]);
                *reinterpret_cast<float4*>(
                    Cout + cbo + (size_t)(tj * 128 + r) * NN + ti * 128 + c4 * 4) = v;
            }
        }
    } else {
        __half* Yh = g_Yh + (size_t)b * NN * NN;
        #pragma unroll
        for (int mt = 0; mt < 2; mt++)
            #pragma unroll
            for (int j = 0; j < 8; j++)
                #pragma unroll
                for (int rh = 0; rh < 2; rh++) {
                    float x0 = acc[mt][j][rh * 2], x1 = acc[mt][j][rh * 2 + 1];
                    float v0 = 0.07f * x0 + EPSF;
                    float v1 = 0.07f * x1 + EPSF;
                    int gmL = wm * 32 + mt * 16 + (lane >> 2) + rh * 8;
                    int gnL = wn * 64 + j * 8 + (lane & 3) * 2;
                    __half2 hv = __floats2half2_rn(v0, v1);
                    *reinterpret_cast<__half2*>(
                        Yh + (size_t)(ti * 128 + gmL) * NN + tj * 128 + gnL) = hv;
                    if (ti != tj) {
                        trans[gnL * 132 + gmL] = v0;
                        trans[(gnL + 1) * 132 + gmL] = v1;
                    }
                }
        __syncthreads();
        if (ti != tj) {
            #pragma unroll
            for (int i = 0; i < 16; i++) {
                int flat = tid + i * 256;
                int r = flat >> 5, c4 = flat & 31;
                const float* tr = trans + r * 132 + c4 * 4;
                __half2 h0 = __floats2half2_rn(tr[0], tr[1]);
                __half2 h1 = __floats2half2_rn(tr[2], tr[3]);
                uint2 pk;
                pk.x = *reinterpret_cast<uint32_t*>(&h0);
                pk.y = *reinterpret_cast<uint32_t*>(&h1);
                *reinterpret_cast<uint2*>(
                    Yh + (size_t)(tj * 128 + r) * NN + ti * 128 + c4 * 4) = pk;
            }
        }
    }
}

// ---------------------------------------------------------------------------
// Kernel 3: per-row: y=l2norm(Y); u=l2norm(|0.5*SW+sqrt(y)|+EPS); out *= u
// half2-vectorized loads.
// ---------------------------------------------------------------------------
__global__ void __launch_bounds__(256) final_kernel(float* __restrict__ out)
{
    int row = blockIdx.x;
    int tid = threadIdx.x;
    const __half2* y2 = reinterpret_cast<const __half2*>(g_Yh + (size_t)row * NN);
    const __half2* s2p = reinterpret_cast<const __half2*>(g_SWf + (size_t)row * NN);
    float2* o2 = reinterpret_cast<float2*>(out + (size_t)row * NN);

    __shared__ float red[8];

    float2 yv[2], swv[2];
    float s1 = 0.0f;
    #pragma unroll
    for (int j = 0; j < 2; j++) {
        int m2 = tid + j * 256;
        yv[j] = __half22float2(y2[m2]);
        swv[j] = __half22float2(s2p[m2]);
        s1 += yv[j].x * yv[j].x + yv[j].y * yv[j].y;
    }
    #pragma unroll
    for (int o = 16; o > 0; o >>= 1) s1 += __shfl_xor_sync(0xffffffffu, s1, o);
    if ((tid & 31) == 0) red[tid >> 5] = s1;
    __syncthreads();
    float yt = 0.0f;
    #pragma unroll
    for (int w = 0; w < 8; w++) yt += red[w];
    float yin = rsqrtf(fmaxf(yt, 1e-24f));
    __syncthreads();

    float tv[2][2];
    float s2 = 0.0f;
    #pragma unroll
    for (int j = 0; j < 2; j++) {
        float t0 = fabsf(0.5f * swv[j].x + sqrtf(yv[j].x * yin)) + EPSF;
        float t1 = fabsf(0.5f * swv[j].y + sqrtf(yv[j].y * yin)) + EPSF;
        tv[j][0] = t0; tv[j][1] = t1;
        s2 += t0 * t0 + t1 * t1;
    }
    #pragma unroll
    for (int o = 16; o > 0; o >>= 1) s2 += __shfl_xor_sync(0xffffffffu, s2, o);
    if ((tid & 31) == 0) red[tid >> 5] = s2;
    __syncthreads();
    float tt = 0.0f;
    #pragma unroll
    for (int w = 0; w < 8; w++) tt += red[w];
    float tin = rsqrtf(fmaxf(tt, 1e-24f));

    #pragma unroll
    for (int j = 0; j < 2; j++) {
        int m2 = tid + j * 256;
        float2 ov = o2[m2];
        ov.x *= tv[j][0] * tin;
        ov.y *= tv[j][1] * tin;
        o2[m2] = ov;
    }
}

// ---------------------------------------------------------------------------
extern "C" void kernel_launch(void* const* d_in, const int* in_sizes, int n_in,
                              void* d_out, int out_size)
{
    const float* context     = (const float*)d_in[0];  // (8,1024,128)
    const float* acc_u       = (const float*)d_in[1];
    const float* acc_v       = (const float*)d_in[2];
    const float* uv_angle    = (const float*)d_in[3];
    const float* uv_angleACC = (const float*)d_in[4];
    const float* speed       = (const float*)d_in[5];
    // d_in[6] = isPhy (unused)
    const float* dist        = (const float*)d_in[7];  // (1024,1024)
    const float* angle       = (const float*)d_in[8];  // (1024,1024)
    const float* weight      = (const float*)d_in[9];  // (16,128)
    float* out = (float*)d_out;                        // (8,1024,1024)

    cudaFuncSetAttribute((const void*)&syrk_mma_kernel,
                         cudaFuncAttributeMaxDynamicSharedMemorySize, SYRK_SMEM);

    prep_kernel<<<2048, 256>>>(context, weight, acc_u, acc_v,
                               uv_angle, uv_angleACC, speed, dist, angle);
    syrk_mma_kernel<<<2 * NB * NPAIRS, 256, SYRK_SMEM>>>(out);
    final_kernel<<<NB * NN, 256>>>(out);
}